// round 1
// baseline (speedup 1.0000x reference)
#include <cuda_runtime.h>

#define N_INST 200000
#define N_NETN 50000
#define NN     250000
#define NE     2000000

// ---------------- device scratch (no runtime allocation allowed) ----------------
__device__ float g_xf[(size_t)NN * 64];   // x_f = h @ Wf + bf
__device__ float g_xr[(size_t)NN * 64];   // x_r = h @ Wr + br
__device__ float g_acc[(size_t)NN * 64];  // fused scatter accumulator (both dirs)
__device__ float g_disf[NN], g_disr[NN];  // deg^-1/2
__device__ float g_idegf[NN], g_idegr[NN];// deg^-1
__device__ int   g_cntf[NN], g_cntr[NN];  // edge counts

// ---------------- helpers ----------------
__device__ __forceinline__ float leaky(float v) { return fmaxf(v, 0.1f * v); }

__device__ __forceinline__ unsigned long long dup64(float a) {
    unsigned long long r;
    asm("mov.b64 %0, {%1, %1};" : "=l"(r) : "f"(a));
    return r;
}
__device__ __forceinline__ unsigned long long pk64(float a, float b) {
    unsigned long long r;
    asm("mov.b64 %0, {%1, %2};" : "=l"(r) : "f"(a), "f"(b));
    return r;
}
__device__ __forceinline__ float2 up64(unsigned long long v) {
    float2 r;
    asm("mov.b64 {%0, %1}, %2;" : "=f"(r.x), "=f"(r.y) : "l"(v));
    return r;
}
__device__ __forceinline__ void fma2(unsigned long long& d,
                                     unsigned long long a,
                                     unsigned long long b) {
    asm("fma.rn.f32x2 %0, %1, %2, %0;" : "+l"(d) : "l"(a), "l"(b));
}
__device__ __forceinline__ void red4(float* p, float4 v) {
    asm volatile("red.global.add.v4.f32 [%0], {%1, %2, %3, %4};"
                 :: "l"(p), "f"(v.x), "f"(v.y), "f"(v.z), "f"(v.w) : "memory");
}

// ---------------- degree counting ----------------
__global__ __launch_bounds__(256) void k_count(const int* __restrict__ ei) {
    int e = blockIdx.x * 256 + threadIdx.x;
    if (e >= NE) return;
    atomicAdd(&g_cntf[ei[e]], 1);
    atomicAdd(&g_cntr[ei[NE + e]], 1);
}

__global__ __launch_bounds__(256) void k_deg() {
    int n = blockIdx.x * 256 + threadIdx.x;
    if (n >= NN) return;
    float df = (float)g_cntf[n] + 1.0f;
    float dr = (float)g_cntr[n] + 1.0f;
    g_disf[n] = rsqrtf(df);
    g_disr[n] = rsqrtf(dr);
    g_idegf[n] = 1.0f / df;
    g_idegr[n] = 1.0f / dr;
}

// ---------------- instance encoder: x[200k,16] -> 128 -> 64 (leaky both) ----------------
__global__ __launch_bounds__(256) void k_enc_inst(
    const float* __restrict__ x,
    const float* __restrict__ W1, const float* __restrict__ b1,
    const float* __restrict__ W2, const float* __restrict__ b2,
    float* __restrict__ out)
{
    __shared__ float W1s[16 * 128];
    __shared__ float W2s[128 * 64];
    __shared__ float b1s[128];
    __shared__ float b2s[64];
    __shared__ float xs[8][16];
    __shared__ float Ts[8][128];
    int tid = threadIdx.x;
    int base = blockIdx.x * 8;
#pragma unroll
    for (int i = 0; i < 8; i++)  W1s[tid + i * 256] = W1[tid + i * 256];
#pragma unroll
    for (int i = 0; i < 32; i++) W2s[tid + i * 256] = W2[tid + i * 256];
    if (tid < 128) b1s[tid] = b1[tid];
    else if (tid < 192) b2s[tid - 128] = b2[tid - 128];
    if (tid < 128) {
        int n = tid >> 4, k = tid & 15;
        xs[n][k] = x[(size_t)(base + n) * 16 + k];
    }
    __syncthreads();
    // phase A: T = leaky(x @ W1 + b1)
#pragma unroll
    for (int i = 0; i < 4; i++) {
        int idx = tid + i * 256;
        int n = idx >> 7, j = idx & 127;
        float a = b1s[j];
#pragma unroll
        for (int k = 0; k < 16; k++) a += xs[n][k] * W1s[k * 128 + j];
        Ts[n][j] = leaky(a);
    }
    __syncthreads();
    // phase B: out = leaky(T @ W2 + b2); warp per node, lane owns features (2l, 2l+1)
    int w = tid >> 5, lane = tid & 31;
    float2 bb = *(const float2*)&b2s[2 * lane];
    unsigned long long acc = pk64(bb.x, bb.y);
#pragma unroll 8
    for (int j = 0; j < 128; j += 4) {
        float4 t = *(const float4*)&Ts[w][j];
        fma2(acc, dup64(t.x), *(const unsigned long long*)&W2s[(j + 0) * 64 + 2 * lane]);
        fma2(acc, dup64(t.y), *(const unsigned long long*)&W2s[(j + 1) * 64 + 2 * lane]);
        fma2(acc, dup64(t.z), *(const unsigned long long*)&W2s[(j + 2) * 64 + 2 * lane]);
        fma2(acc, dup64(t.w), *(const unsigned long long*)&W2s[(j + 3) * 64 + 2 * lane]);
    }
    float2 o = up64(acc);
    float2 ov = make_float2(leaky(o.x), leaky(o.y));
    *(float2*)&out[(size_t)(base + w) * 256 + 2 * lane] = ov;
}

// ---------------- net encoder: x_net[50k,8] -> 64 -> 64 ----------------
__global__ __launch_bounds__(256) void k_enc_net(
    const float* __restrict__ x,
    const float* __restrict__ W1, const float* __restrict__ b1,
    const float* __restrict__ W2, const float* __restrict__ b2,
    float* __restrict__ out)
{
    __shared__ float W1s[8 * 64];
    __shared__ float W2s[64 * 64];
    __shared__ float b1s[64];
    __shared__ float b2s[64];
    __shared__ float xs[8][8];
    __shared__ float Ts[8][64];
    int tid = threadIdx.x;
    int base = blockIdx.x * 8;
#pragma unroll
    for (int i = 0; i < 2; i++)  W1s[tid + i * 256] = W1[tid + i * 256];
#pragma unroll
    for (int i = 0; i < 16; i++) W2s[tid + i * 256] = W2[tid + i * 256];
    if (tid < 64) b1s[tid] = b1[tid];
    else if (tid < 128) b2s[tid - 64] = b2[tid - 64];
    if (tid < 64) {
        int n = tid >> 3, k = tid & 7;
        xs[n][k] = x[(size_t)(base + n) * 8 + k];
    }
    __syncthreads();
#pragma unroll
    for (int i = 0; i < 2; i++) {
        int idx = tid + i * 256;
        int n = idx >> 6, j = idx & 63;
        float a = b1s[j];
#pragma unroll
        for (int k = 0; k < 8; k++) a += xs[n][k] * W1s[k * 64 + j];
        Ts[n][j] = leaky(a);
    }
    __syncthreads();
    int w = tid >> 5, lane = tid & 31;
    float2 bb = *(const float2*)&b2s[2 * lane];
    unsigned long long acc = pk64(bb.x, bb.y);
#pragma unroll 8
    for (int j = 0; j < 64; j += 4) {
        float4 t = *(const float4*)&Ts[w][j];
        fma2(acc, dup64(t.x), *(const unsigned long long*)&W2s[(j + 0) * 64 + 2 * lane]);
        fma2(acc, dup64(t.y), *(const unsigned long long*)&W2s[(j + 1) * 64 + 2 * lane]);
        fma2(acc, dup64(t.z), *(const unsigned long long*)&W2s[(j + 2) * 64 + 2 * lane]);
        fma2(acc, dup64(t.w), *(const unsigned long long*)&W2s[(j + 3) * 64 + 2 * lane]);
    }
    float2 o = up64(acc);
    float2 ov = make_float2(leaky(o.x), leaky(o.y));
    *(float2*)&out[(size_t)(N_INST + base + w) * 256 + 2 * lane] = ov;
}

// ---------------- dual GEMM: x_f = h@Wf+bf, x_r = h@Wr+br ----------------
// h read from d_out (row stride 256 floats, column offset loff). 64-node tile.
__global__ __launch_bounds__(256) void k_gemm(
    const float* __restrict__ hsrc, int loff,
    const float* __restrict__ Wf, const float* __restrict__ bf,
    const float* __restrict__ Wr, const float* __restrict__ br)
{
    __shared__ float hs[64 * 64];   // transposed, swizzled: hs[k][(n+k)&63]
    __shared__ float wfs[64 * 64];
    __shared__ float wrs[64 * 64];
    int tid = threadIdx.x;
    int base = blockIdx.x * 64;
#pragma unroll
    for (int i = 0; i < 16; i++) {
        wfs[tid + i * 256] = Wf[tid + i * 256];
        wrs[tid + i * 256] = Wr[tid + i * 256];
    }
    {
        int r = tid >> 6, c = tid & 63;
#pragma unroll
        for (int i = 0; i < 16; i++) {
            int nl = i * 4 + r;
            int g = base + nl;
            float v = (g < NN) ? hsrc[(size_t)g * 256 + loff + c] : 0.0f;
            hs[c * 64 + ((nl + c) & 63)] = v;   // conflict-free transpose write
        }
    }
    __syncthreads();
    int tx = tid & 15, ty = tid >> 4;
    int bn = ty * 4;
    unsigned long long cf[4][2] = {}, cr[4][2] = {};
#pragma unroll 8
    for (int k = 0; k < 64; k++) {
        unsigned long long wf0 = *(const unsigned long long*)&wfs[k * 64 + tx * 4];
        unsigned long long wf1 = *(const unsigned long long*)&wfs[k * 64 + tx * 4 + 2];
        unsigned long long wr0 = *(const unsigned long long*)&wrs[k * 64 + tx * 4];
        unsigned long long wr1 = *(const unsigned long long*)&wrs[k * 64 + tx * 4 + 2];
#pragma unroll
        for (int i = 0; i < 4; i++) {
            unsigned long long ad = dup64(hs[k * 64 + ((bn + i + k) & 63)]);
            fma2(cf[i][0], ad, wf0); fma2(cf[i][1], ad, wf1);
            fma2(cr[i][0], ad, wr0); fma2(cr[i][1], ad, wr1);
        }
    }
    float4 bfv = *(const float4*)&bf[tx * 4];
    float4 brv = *(const float4*)&br[tx * 4];
#pragma unroll
    for (int i = 0; i < 4; i++) {
        int g = base + bn + i;
        if (g < NN) {
            float2 lo = up64(cf[i][0]), hi = up64(cf[i][1]);
            float4 v = make_float4(lo.x + bfv.x, lo.y + bfv.y, hi.x + bfv.z, hi.y + bfv.w);
            *(float4*)&g_xf[(size_t)g * 64 + tx * 4] = v;
            lo = up64(cr[i][0]); hi = up64(cr[i][1]);
            float4 u = make_float4(lo.x + brv.x, lo.y + brv.y, hi.x + brv.z, hi.y + brv.w);
            *(float4*)&g_xr[(size_t)g * 64 + tx * 4] = u;
        }
    }
}

// ---------------- edge kernel: fused forward+reverse message + scatter ----------------
// 16 threads per edge, each handles one float4 slice.
__global__ __launch_bounds__(256) void k_edge(const int* __restrict__ ei) {
    unsigned int t = blockIdx.x * 256u + threadIdx.x;
    unsigned int e = t >> 4;
    int q = (t & 15) * 4;
    if (e >= NE) return;
    int a = __ldg(ei + e);
    int b = __ldg(ei + NE + e);
    float nf = __ldg(&g_disf[a]) * __ldg(&g_disf[b]);   // forward norm
    float nr = __ldg(&g_disr[b]) * __ldg(&g_disr[a]);   // reverse norm
    float4 vf = *(const float4*)&g_xf[(size_t)a * 64 + q];
    float4 mf = make_float4(fmaxf(vf.x, 0.f) * nf, fmaxf(vf.y, 0.f) * nf,
                            fmaxf(vf.z, 0.f) * nf, fmaxf(vf.w, 0.f) * nf);
    red4(&g_acc[(size_t)b * 64 + q], mf);
    float4 vr = *(const float4*)&g_xr[(size_t)b * 64 + q];
    float4 mr = make_float4(fmaxf(vr.x, 0.f) * nr, fmaxf(vr.y, 0.f) * nr,
                            fmaxf(vr.z, 0.f) * nr, fmaxf(vr.w, 0.f) * nr);
    red4(&g_acc[(size_t)a * 64 + q], mr);
}

// ---------------- epilogue: self terms + LayerNorm + leaky -> d_out ----------------
__global__ __launch_bounds__(256) void k_epi(
    const float* __restrict__ rootf, const float* __restrict__ rootr,
    const float* __restrict__ lg, const float* __restrict__ lb,
    float* __restrict__ out, int off)
{
    int n = blockIdx.x * 8 + (threadIdx.x >> 5);
    if (n >= NN) return;
    int lane = threadIdx.x & 31;
    int d = lane * 2;
    size_t o64 = (size_t)n * 64 + d;
    float2 ac = *(const float2*)&g_acc[o64];
    float2 fx = *(const float2*)&g_xf[o64];
    float2 rx = *(const float2*)&g_xr[o64];
    float idf = g_idegf[n], idr = g_idegr[n];
    float s0 = ac.x + fmaxf(fx.x + rootf[d], 0.f) * idf + fmaxf(rx.x + rootr[d], 0.f) * idr;
    float s1 = ac.y + fmaxf(fx.y + rootf[d + 1], 0.f) * idf + fmaxf(rx.y + rootr[d + 1], 0.f) * idr;
    float sum = s0 + s1;
#pragma unroll
    for (int o = 16; o > 0; o >>= 1) sum += __shfl_xor_sync(0xffffffffu, sum, o);
    float m = sum * (1.0f / 64.0f);
    float d0 = s0 - m, d1 = s1 - m;
    float sq = d0 * d0 + d1 * d1;
#pragma unroll
    for (int o = 16; o > 0; o >>= 1) sq += __shfl_xor_sync(0xffffffffu, sq, o);
    float inv = rsqrtf(sq * (1.0f / 64.0f) + 1e-5f);
    float o0 = leaky(d0 * inv * lg[d] + lb[d]);
    float o1 = leaky(d1 * inv * lg[d + 1] + lb[d + 1]);
    *(float2*)&out[(size_t)n * 256 + off + d] = make_float2(o0, o1);
}

// ---------------- launch ----------------
extern "C" void kernel_launch(void* const* d_in, const int* in_sizes, int n_in,
                              void* d_out, int out_size) {
    const float* x     = (const float*)d_in[0];
    const float* xnet  = (const float*)d_in[1];
    const int*   ei    = (const int*)  d_in[2];
    const float* e1W   = (const float*)d_in[3];
    const float* e1b   = (const float*)d_in[4];
    const float* e2W   = (const float*)d_in[5];
    const float* e2b   = (const float*)d_in[6];
    const float* n1W   = (const float*)d_in[7];
    const float* n1b   = (const float*)d_in[8];
    const float* n2W   = (const float*)d_in[9];
    const float* n2b   = (const float*)d_in[10];
    const float* convW = (const float*)d_in[11];
    const float* convb = (const float*)d_in[12];
    const float* convr = (const float*)d_in[13];
    const float* reW   = (const float*)d_in[14];
    const float* reb   = (const float*)d_in[15];
    const float* rer   = (const float*)d_in[16];
    const float* lng   = (const float*)d_in[17];
    const float* lnb   = (const float*)d_in[18];
    float* out = (float*)d_out;

    void *pcf, *pcr, *pacc;
    cudaGetSymbolAddress(&pcf,  g_cntf);
    cudaGetSymbolAddress(&pcr,  g_cntr);
    cudaGetSymbolAddress(&pacc, g_acc);

    cudaMemsetAsync(pcf, 0, NN * sizeof(int));
    cudaMemsetAsync(pcr, 0, NN * sizeof(int));
    k_count<<<(NE + 255) / 256, 256>>>(ei);
    k_deg<<<(NN + 255) / 256, 256>>>();

    k_enc_inst<<<N_INST / 8, 256>>>(x, e1W, e1b, e2W, e2b, out);
    k_enc_net<<<N_NETN / 8, 256>>>(xnet, n1W, n1b, n2W, n2b, out);

    for (int l = 0; l < 3; l++) {
        k_gemm<<<(NN + 63) / 64, 256>>>(out, l * 64,
                                        convW + l * 4096, convb + l * 64,
                                        reW + l * 4096,   reb + l * 64);
        cudaMemsetAsync(pacc, 0, (size_t)NN * 64 * sizeof(float));
        k_edge<<<NE / 16, 256>>>(ei);
        k_epi<<<(NN + 7) / 8, 256>>>(convr + l * 64, rer + l * 64,
                                     lng + l * 64, lnb + l * 64,
                                     out, (l + 1) * 64);
    }
}

// round 2
// speedup vs baseline: 1.1862x; 1.1862x over previous
#include <cuda_runtime.h>

#define N_INST 200000
#define N_NETN 50000
#define NN     250000
#define NE     2000000
#define NSCANB 245   // ceil(250000/1024)

// ---------------- device scratch (no runtime allocation allowed) ----------------
__device__ float g_xf[(size_t)NN * 64];   // x_f = h @ Wf + bf
__device__ float g_xr[(size_t)NN * 64];   // x_r = h @ Wr + br
__device__ float g_acc[(size_t)NN * 64];  // forward aggregation result
__device__ float g_disf[NN], g_disr[NN];  // deg^-1/2
__device__ float g_idegf[NN], g_idegr[NN];// deg^-1
__device__ int   g_cntf[NN], g_cntr[NN];  // edge counts (row / col)
__device__ int   g_offF[NN], g_offR[NN];  // CSR bucket starts
__device__ int   g_fillF[NN], g_fillR[NN];
__device__ int   g_bsF[256], g_bsR[256];  // scan block sums
__device__ int2  g_csrF[NE];              // (src, norm) bucketed by col (fwd target)
__device__ int2  g_csrR[NE];              // (src, norm) bucketed by row (rev target)

// ---------------- helpers ----------------
__device__ __forceinline__ float leaky(float v) { return fmaxf(v, 0.1f * v); }

__device__ __forceinline__ unsigned long long dup64(float a) {
    unsigned long long r;
    asm("mov.b64 %0, {%1, %1};" : "=l"(r) : "f"(a));
    return r;
}
__device__ __forceinline__ unsigned long long pk64(float a, float b) {
    unsigned long long r;
    asm("mov.b64 %0, {%1, %2};" : "=l"(r) : "f"(a), "f"(b));
    return r;
}
__device__ __forceinline__ float2 up64(unsigned long long v) {
    float2 r;
    asm("mov.b64 {%0, %1}, %2;" : "=f"(r.x), "=f"(r.y) : "l"(v));
    return r;
}
__device__ __forceinline__ void fma2(unsigned long long& d,
                                     unsigned long long a,
                                     unsigned long long b) {
    asm("fma.rn.f32x2 %0, %1, %2, %0;" : "+l"(d) : "l"(a), "l"(b));
}

// ---------------- degree counting ----------------
__global__ __launch_bounds__(256) void k_count(const int* __restrict__ ei) {
    int e = blockIdx.x * 256 + threadIdx.x;
    if (e >= NE) return;
    atomicAdd(&g_cntf[ei[e]], 1);
    atomicAdd(&g_cntr[ei[NE + e]], 1);
}

__global__ __launch_bounds__(256) void k_deg() {
    int n = blockIdx.x * 256 + threadIdx.x;
    if (n >= NN) return;
    float df = (float)g_cntf[n] + 1.0f;
    float dr = (float)g_cntr[n] + 1.0f;
    g_disf[n] = rsqrtf(df);
    g_disr[n] = rsqrtf(dr);
    g_idegf[n] = 1.0f / df;
    g_idegr[n] = 1.0f / dr;
}

// ---------------- exclusive scan (3 kernels, 1024 elems/block) ----------------
__global__ __launch_bounds__(256) void k_scan1(const int* __restrict__ cnt,
                                               int* __restrict__ off,
                                               int* __restrict__ bsum) {
    __shared__ int wsum[8];
    int tid = threadIdx.x, lane = tid & 31, w = tid >> 5;
    int base = blockIdx.x * 1024 + tid * 4;
    int v0 = (base + 0 < NN) ? cnt[base + 0] : 0;
    int v1 = (base + 1 < NN) ? cnt[base + 1] : 0;
    int v2 = (base + 2 < NN) ? cnt[base + 2] : 0;
    int v3 = (base + 3 < NN) ? cnt[base + 3] : 0;
    int s = v0 + v1 + v2 + v3;
    int x = s;
#pragma unroll
    for (int o = 1; o < 32; o <<= 1) {
        int y = __shfl_up_sync(0xffffffffu, x, o);
        if (lane >= o) x += y;
    }
    if (lane == 31) wsum[w] = x;
    __syncthreads();
    if (tid == 0) {
        int r = 0;
#pragma unroll
        for (int j = 0; j < 8; j++) { int t = wsum[j]; wsum[j] = r; r += t; }
        bsum[blockIdx.x] = r;
    }
    __syncthreads();
    int ex = wsum[w] + x - s;
    if (base + 0 < NN) off[base + 0] = ex;
    if (base + 1 < NN) off[base + 1] = ex + v0;
    if (base + 2 < NN) off[base + 2] = ex + v0 + v1;
    if (base + 3 < NN) off[base + 3] = ex + v0 + v1 + v2;
}

__global__ __launch_bounds__(256) void k_scan2(int* __restrict__ bsum, int nb) {
    __shared__ int sm[256];
    int tid = threadIdx.x;
    int v = (tid < nb) ? bsum[tid] : 0;
    sm[tid] = v;
    __syncthreads();
#pragma unroll
    for (int o = 1; o < 256; o <<= 1) {
        int t = (tid >= o) ? sm[tid - o] : 0;
        __syncthreads();
        sm[tid] += t;
        __syncthreads();
    }
    if (tid < nb) bsum[tid] = sm[tid] - v;   // exclusive
}

__global__ __launch_bounds__(256) void k_scan3(int* __restrict__ off,
                                               const int* __restrict__ bsum) {
    int add = bsum[blockIdx.x];
    int base = blockIdx.x * 1024 + threadIdx.x * 4;
#pragma unroll
    for (int i = 0; i < 4; i++)
        if (base + i < NN) off[base + i] += add;
}

// ---------------- CSR placement with per-edge norms ----------------
__global__ __launch_bounds__(256) void k_place(const int* __restrict__ ei) {
    int e = blockIdx.x * 256 + threadIdx.x;
    if (e >= NE) return;
    int a = __ldg(ei + e);
    int b = __ldg(ei + NE + e);
    float nf = __ldg(&g_disf[a]) * __ldg(&g_disf[b]);
    float nr = __ldg(&g_disr[b]) * __ldg(&g_disr[a]);
    int pf = g_offF[b] + atomicAdd(&g_fillF[b], 1);
    g_csrF[pf] = make_int2(a, __float_as_int(nf));
    int pr = g_offR[a] + atomicAdd(&g_fillR[a], 1);
    g_csrR[pr] = make_int2(b, __float_as_int(nr));
}

// ---------------- instance encoder: x[200k,16] -> 128 -> 64 (leaky both) ----------------
__global__ __launch_bounds__(256) void k_enc_inst(
    const float* __restrict__ x,
    const float* __restrict__ W1, const float* __restrict__ b1,
    const float* __restrict__ W2, const float* __restrict__ b2,
    float* __restrict__ out)
{
    __shared__ float W1s[16 * 128];
    __shared__ float W2s[128 * 64];
    __shared__ float b1s[128];
    __shared__ float b2s[64];
    __shared__ float xs[8][16];
    __shared__ float Ts[8][128];
    int tid = threadIdx.x;
    int base = blockIdx.x * 8;
#pragma unroll
    for (int i = 0; i < 8; i++)  W1s[tid + i * 256] = W1[tid + i * 256];
#pragma unroll
    for (int i = 0; i < 32; i++) W2s[tid + i * 256] = W2[tid + i * 256];
    if (tid < 128) b1s[tid] = b1[tid];
    else if (tid < 192) b2s[tid - 128] = b2[tid - 128];
    if (tid < 128) {
        int n = tid >> 4, k = tid & 15;
        xs[n][k] = x[(size_t)(base + n) * 16 + k];
    }
    __syncthreads();
#pragma unroll
    for (int i = 0; i < 4; i++) {
        int idx = tid + i * 256;
        int n = idx >> 7, j = idx & 127;
        float a = b1s[j];
#pragma unroll
        for (int k = 0; k < 16; k++) a += xs[n][k] * W1s[k * 128 + j];
        Ts[n][j] = leaky(a);
    }
    __syncthreads();
    int w = tid >> 5, lane = tid & 31;
    float2 bb = *(const float2*)&b2s[2 * lane];
    unsigned long long acc = pk64(bb.x, bb.y);
#pragma unroll 8
    for (int j = 0; j < 128; j += 4) {
        float4 t = *(const float4*)&Ts[w][j];
        fma2(acc, dup64(t.x), *(const unsigned long long*)&W2s[(j + 0) * 64 + 2 * lane]);
        fma2(acc, dup64(t.y), *(const unsigned long long*)&W2s[(j + 1) * 64 + 2 * lane]);
        fma2(acc, dup64(t.z), *(const unsigned long long*)&W2s[(j + 2) * 64 + 2 * lane]);
        fma2(acc, dup64(t.w), *(const unsigned long long*)&W2s[(j + 3) * 64 + 2 * lane]);
    }
    float2 o = up64(acc);
    float2 ov = make_float2(leaky(o.x), leaky(o.y));
    *(float2*)&out[(size_t)(base + w) * 256 + 2 * lane] = ov;
}

// ---------------- net encoder: x_net[50k,8] -> 64 -> 64 ----------------
__global__ __launch_bounds__(256) void k_enc_net(
    const float* __restrict__ x,
    const float* __restrict__ W1, const float* __restrict__ b1,
    const float* __restrict__ W2, const float* __restrict__ b2,
    float* __restrict__ out)
{
    __shared__ float W1s[8 * 64];
    __shared__ float W2s[64 * 64];
    __shared__ float b1s[64];
    __shared__ float b2s[64];
    __shared__ float xs[8][8];
    __shared__ float Ts[8][64];
    int tid = threadIdx.x;
    int base = blockIdx.x * 8;
#pragma unroll
    for (int i = 0; i < 2; i++)  W1s[tid + i * 256] = W1[tid + i * 256];
#pragma unroll
    for (int i = 0; i < 16; i++) W2s[tid + i * 256] = W2[tid + i * 256];
    if (tid < 64) b1s[tid] = b1[tid];
    else if (tid < 128) b2s[tid - 64] = b2[tid - 64];
    if (tid < 64) {
        int n = tid >> 3, k = tid & 7;
        xs[n][k] = x[(size_t)(base + n) * 8 + k];
    }
    __syncthreads();
#pragma unroll
    for (int i = 0; i < 2; i++) {
        int idx = tid + i * 256;
        int n = idx >> 6, j = idx & 63;
        float a = b1s[j];
#pragma unroll
        for (int k = 0; k < 8; k++) a += xs[n][k] * W1s[k * 64 + j];
        Ts[n][j] = leaky(a);
    }
    __syncthreads();
    int w = tid >> 5, lane = tid & 31;
    float2 bb = *(const float2*)&b2s[2 * lane];
    unsigned long long acc = pk64(bb.x, bb.y);
#pragma unroll 8
    for (int j = 0; j < 64; j += 4) {
        float4 t = *(const float4*)&Ts[w][j];
        fma2(acc, dup64(t.x), *(const unsigned long long*)&W2s[(j + 0) * 64 + 2 * lane]);
        fma2(acc, dup64(t.y), *(const unsigned long long*)&W2s[(j + 1) * 64 + 2 * lane]);
        fma2(acc, dup64(t.z), *(const unsigned long long*)&W2s[(j + 2) * 64 + 2 * lane]);
        fma2(acc, dup64(t.w), *(const unsigned long long*)&W2s[(j + 3) * 64 + 2 * lane]);
    }
    float2 o = up64(acc);
    float2 ov = make_float2(leaky(o.x), leaky(o.y));
    *(float2*)&out[(size_t)(N_INST + base + w) * 256 + 2 * lane] = ov;
}

// ---------------- dual GEMM: x_f = h@Wf+bf, x_r = h@Wr+br ----------------
__global__ __launch_bounds__(256) void k_gemm(
    const float* __restrict__ hsrc, int loff,
    const float* __restrict__ Wf, const float* __restrict__ bf,
    const float* __restrict__ Wr, const float* __restrict__ br)
{
    __shared__ float hs[64 * 64];   // transposed, swizzled: hs[k][(n+k)&63]
    __shared__ float wfs[64 * 64];
    __shared__ float wrs[64 * 64];
    int tid = threadIdx.x;
    int base = blockIdx.x * 64;
#pragma unroll
    for (int i = 0; i < 16; i++) {
        wfs[tid + i * 256] = Wf[tid + i * 256];
        wrs[tid + i * 256] = Wr[tid + i * 256];
    }
    {
        int r = tid >> 6, c = tid & 63;
#pragma unroll
        for (int i = 0; i < 16; i++) {
            int nl = i * 4 + r;
            int g = base + nl;
            float v = (g < NN) ? hsrc[(size_t)g * 256 + loff + c] : 0.0f;
            hs[c * 64 + ((nl + c) & 63)] = v;
        }
    }
    __syncthreads();
    int tx = tid & 15, ty = tid >> 4;
    int bn = ty * 4;
    unsigned long long cf[4][2] = {}, cr[4][2] = {};
#pragma unroll 8
    for (int k = 0; k < 64; k++) {
        unsigned long long wf0 = *(const unsigned long long*)&wfs[k * 64 + tx * 4];
        unsigned long long wf1 = *(const unsigned long long*)&wfs[k * 64 + tx * 4 + 2];
        unsigned long long wr0 = *(const unsigned long long*)&wrs[k * 64 + tx * 4];
        unsigned long long wr1 = *(const unsigned long long*)&wrs[k * 64 + tx * 4 + 2];
#pragma unroll
        for (int i = 0; i < 4; i++) {
            unsigned long long ad = dup64(hs[k * 64 + ((bn + i + k) & 63)]);
            fma2(cf[i][0], ad, wf0); fma2(cf[i][1], ad, wf1);
            fma2(cr[i][0], ad, wr0); fma2(cr[i][1], ad, wr1);
        }
    }
    float4 bfv = *(const float4*)&bf[tx * 4];
    float4 brv = *(const float4*)&br[tx * 4];
#pragma unroll
    for (int i = 0; i < 4; i++) {
        int g = base + bn + i;
        if (g < NN) {
            float2 lo = up64(cf[i][0]), hi = up64(cf[i][1]);
            float4 v = make_float4(lo.x + bfv.x, lo.y + bfv.y, hi.x + bfv.z, hi.y + bfv.w);
            *(float4*)&g_xf[(size_t)g * 64 + tx * 4] = v;
            lo = up64(cr[i][0]); hi = up64(cr[i][1]);
            float4 u = make_float4(lo.x + brv.x, lo.y + brv.y, hi.x + brv.z, hi.y + brv.w);
            *(float4*)&g_xr[(size_t)g * 64 + tx * 4] = u;
        }
    }
}

// ---------------- forward pull aggregation: acc[n] = sum norm*relu(xf[src]) ----------------
__global__ __launch_bounds__(256) void k_aggF() {
    int n = blockIdx.x * 8 + (threadIdx.x >> 5);
    int lane = threadIdx.x & 31;
    int d = lane * 2;
    int beg = g_offF[n];
    int deg = g_cntr[n];          // fwd buckets are keyed by col -> cntr
    const int2* cs = g_csrF + beg;
    float2 acc = make_float2(0.f, 0.f);
    int i = 0;
    for (; i + 2 <= deg; i += 2) {
        int2 e0 = __ldg(cs + i), e1 = __ldg(cs + i + 1);
        float2 v0 = *(const float2*)&g_xf[(size_t)e0.x * 64 + d];
        float2 v1 = *(const float2*)&g_xf[(size_t)e1.x * 64 + d];
        float n0 = __int_as_float(e0.y), n1 = __int_as_float(e1.y);
        acc.x += fmaxf(v0.x, 0.f) * n0 + fmaxf(v1.x, 0.f) * n1;
        acc.y += fmaxf(v0.y, 0.f) * n0 + fmaxf(v1.y, 0.f) * n1;
    }
    if (i < deg) {
        int2 e0 = __ldg(cs + i);
        float2 v0 = *(const float2*)&g_xf[(size_t)e0.x * 64 + d];
        float n0 = __int_as_float(e0.y);
        acc.x += fmaxf(v0.x, 0.f) * n0;
        acc.y += fmaxf(v0.y, 0.f) * n0;
    }
    *(float2*)&g_acc[(size_t)n * 64 + d] = acc;
}

// ---------------- reverse pull aggregation + self terms + LayerNorm + leaky ----------------
__global__ __launch_bounds__(256) void k_aggR(
    const float* __restrict__ rootf, const float* __restrict__ rootr,
    const float* __restrict__ lg, const float* __restrict__ lb,
    float* __restrict__ out, int off)
{
    int n = blockIdx.x * 8 + (threadIdx.x >> 5);
    int lane = threadIdx.x & 31;
    int d = lane * 2;
    int beg = g_offR[n];
    int deg = g_cntf[n];          // rev buckets keyed by row -> cntf
    const int2* cs = g_csrR + beg;
    float2 acc = make_float2(0.f, 0.f);
    int i = 0;
    for (; i + 2 <= deg; i += 2) {
        int2 e0 = __ldg(cs + i), e1 = __ldg(cs + i + 1);
        float2 v0 = *(const float2*)&g_xr[(size_t)e0.x * 64 + d];
        float2 v1 = *(const float2*)&g_xr[(size_t)e1.x * 64 + d];
        float n0 = __int_as_float(e0.y), n1 = __int_as_float(e1.y);
        acc.x += fmaxf(v0.x, 0.f) * n0 + fmaxf(v1.x, 0.f) * n1;
        acc.y += fmaxf(v0.y, 0.f) * n0 + fmaxf(v1.y, 0.f) * n1;
    }
    if (i < deg) {
        int2 e0 = __ldg(cs + i);
        float2 v0 = *(const float2*)&g_xr[(size_t)e0.x * 64 + d];
        float n0 = __int_as_float(e0.y);
        acc.x += fmaxf(v0.x, 0.f) * n0;
        acc.y += fmaxf(v0.y, 0.f) * n0;
    }
    size_t o64 = (size_t)n * 64 + d;
    float2 f  = *(const float2*)&g_acc[o64];
    float2 fx = *(const float2*)&g_xf[o64];
    float2 rx = *(const float2*)&g_xr[o64];
    float idf = g_idegf[n], idr = g_idegr[n];
    float s0 = acc.x + f.x + fmaxf(fx.x + rootf[d], 0.f) * idf
                           + fmaxf(rx.x + rootr[d], 0.f) * idr;
    float s1 = acc.y + f.y + fmaxf(fx.y + rootf[d + 1], 0.f) * idf
                           + fmaxf(rx.y + rootr[d + 1], 0.f) * idr;
    float sum = s0 + s1;
#pragma unroll
    for (int o = 16; o > 0; o >>= 1) sum += __shfl_xor_sync(0xffffffffu, sum, o);
    float m = sum * (1.0f / 64.0f);
    float d0 = s0 - m, d1 = s1 - m;
    float sq = d0 * d0 + d1 * d1;
#pragma unroll
    for (int o = 16; o > 0; o >>= 1) sq += __shfl_xor_sync(0xffffffffu, sq, o);
    float inv = rsqrtf(sq * (1.0f / 64.0f) + 1e-5f);
    float o0 = leaky(d0 * inv * lg[d] + lb[d]);
    float o1 = leaky(d1 * inv * lg[d + 1] + lb[d + 1]);
    *(float2*)&out[(size_t)n * 256 + off + d] = make_float2(o0, o1);
}

// ---------------- launch ----------------
extern "C" void kernel_launch(void* const* d_in, const int* in_sizes, int n_in,
                              void* d_out, int out_size) {
    const float* x     = (const float*)d_in[0];
    const float* xnet  = (const float*)d_in[1];
    const int*   ei    = (const int*)  d_in[2];
    const float* e1W   = (const float*)d_in[3];
    const float* e1b   = (const float*)d_in[4];
    const float* e2W   = (const float*)d_in[5];
    const float* e2b   = (const float*)d_in[6];
    const float* n1W   = (const float*)d_in[7];
    const float* n1b   = (const float*)d_in[8];
    const float* n2W   = (const float*)d_in[9];
    const float* n2b   = (const float*)d_in[10];
    const float* convW = (const float*)d_in[11];
    const float* convb = (const float*)d_in[12];
    const float* convr = (const float*)d_in[13];
    const float* reW   = (const float*)d_in[14];
    const float* reb   = (const float*)d_in[15];
    const float* rer   = (const float*)d_in[16];
    const float* lng   = (const float*)d_in[17];
    const float* lnb   = (const float*)d_in[18];
    float* out = (float*)d_out;

    void *pcf, *pcr, *pff, *pfr, *poF, *poR, *pbF, *pbR;
    cudaGetSymbolAddress(&pcf, g_cntf);
    cudaGetSymbolAddress(&pcr, g_cntr);
    cudaGetSymbolAddress(&pff, g_fillF);
    cudaGetSymbolAddress(&pfr, g_fillR);
    cudaGetSymbolAddress(&poF, g_offF);
    cudaGetSymbolAddress(&poR, g_offR);
    cudaGetSymbolAddress(&pbF, g_bsF);
    cudaGetSymbolAddress(&pbR, g_bsR);

    cudaMemsetAsync(pcf, 0, NN * sizeof(int));
    cudaMemsetAsync(pcr, 0, NN * sizeof(int));
    cudaMemsetAsync(pff, 0, NN * sizeof(int));
    cudaMemsetAsync(pfr, 0, NN * sizeof(int));
    k_count<<<(NE + 255) / 256, 256>>>(ei);
    k_deg<<<(NN + 255) / 256, 256>>>();

    // exclusive scans: offF from cntr (fwd targets = col), offR from cntf
    k_scan1<<<NSCANB, 256>>>((const int*)pcr, (int*)poF, (int*)pbF);
    k_scan1<<<NSCANB, 256>>>((const int*)pcf, (int*)poR, (int*)pbR);
    k_scan2<<<1, 256>>>((int*)pbF, NSCANB);
    k_scan2<<<1, 256>>>((int*)pbR, NSCANB);
    k_scan3<<<NSCANB, 256>>>((int*)poF, (const int*)pbF);
    k_scan3<<<NSCANB, 256>>>((int*)poR, (const int*)pbR);
    k_place<<<(NE + 255) / 256, 256>>>(ei);

    k_enc_inst<<<N_INST / 8, 256>>>(x, e1W, e1b, e2W, e2b, out);
    k_enc_net<<<N_NETN / 8, 256>>>(xnet, n1W, n1b, n2W, n2b, out);

    for (int l = 0; l < 3; l++) {
        k_gemm<<<(NN + 63) / 64, 256>>>(out, l * 64,
                                        convW + l * 4096, convb + l * 64,
                                        reW + l * 4096,   reb + l * 64);
        k_aggF<<<NN / 8, 256>>>();
        k_aggR<<<NN / 8, 256>>>(convr + l * 64, rer + l * 64,
                                lng + l * 64, lnb + l * 64,
                                out, (l + 1) * 64);
    }
}

// round 3
// speedup vs baseline: 1.4263x; 1.2024x over previous
#include <cuda_runtime.h>

#define N_INST 200000
#define N_NETN 50000
#define NN     250000
#define NE     2000000
#define NSCANB 245   // ceil(250000/1024)

// ---------------- device scratch (no runtime allocation allowed) ----------------
__device__ float g_xf[(size_t)NN * 64];     // x_f = h @ Wf + bf
__device__ float g_xr[(size_t)NN * 64];     // x_r = h @ Wr + br
__device__ float g_acc[(size_t)NN * 64];    // forward aggregation result
__device__ float g_tmp[(size_t)N_INST * 128]; // encoder hidden (inst)
__device__ float g_tmpn[(size_t)N_NETN * 64]; // encoder hidden (net)
__device__ float g_disf[NN], g_disr[NN];    // deg^-1/2
__device__ float g_idegf[NN], g_idegr[NN];  // deg^-1
__device__ int   g_cntf[NN], g_cntr[NN];    // edge counts (row / col)
__device__ int   g_offF[NN], g_offR[NN];    // CSR bucket starts
__device__ int   g_fillF[NN], g_fillR[NN];
__device__ int   g_bsF[256], g_bsR[256];    // scan block sums
__device__ int2  g_csrF[NE];                // (src, norm) bucketed by col (fwd target)
__device__ int2  g_csrR[NE];                // (src, norm) bucketed by row (rev target)

// ---------------- helpers ----------------
__device__ __forceinline__ float leaky(float v) { return fmaxf(v, 0.1f * v); }

__device__ __forceinline__ unsigned long long dup64(float a) {
    unsigned long long r;
    asm("mov.b64 %0, {%1, %1};" : "=l"(r) : "f"(a));
    return r;
}
__device__ __forceinline__ float2 up64(unsigned long long v) {
    float2 r;
    asm("mov.b64 {%0, %1}, %2;" : "=f"(r.x), "=f"(r.y) : "l"(v));
    return r;
}
__device__ __forceinline__ void fma2(unsigned long long& d,
                                     unsigned long long a,
                                     unsigned long long b) {
    asm("fma.rn.f32x2 %0, %1, %2, %0;" : "+l"(d) : "l"(a), "l"(b));
}

// ---------------- degree counting ----------------
__global__ __launch_bounds__(256) void k_count(const int* __restrict__ ei) {
    int e = blockIdx.x * 256 + threadIdx.x;
    if (e >= NE) return;
    atomicAdd(&g_cntf[ei[e]], 1);
    atomicAdd(&g_cntr[ei[NE + e]], 1);
}

__global__ __launch_bounds__(256) void k_deg() {
    int n = blockIdx.x * 256 + threadIdx.x;
    if (n >= NN) return;
    float df = (float)g_cntf[n] + 1.0f;
    float dr = (float)g_cntr[n] + 1.0f;
    g_disf[n] = rsqrtf(df);
    g_disr[n] = rsqrtf(dr);
    g_idegf[n] = 1.0f / df;
    g_idegr[n] = 1.0f / dr;
}

// ---------------- exclusive scan (3 kernels, 1024 elems/block) ----------------
__global__ __launch_bounds__(256) void k_scan1(const int* __restrict__ cnt,
                                               int* __restrict__ off,
                                               int* __restrict__ bsum) {
    __shared__ int wsum[8];
    int tid = threadIdx.x, lane = tid & 31, w = tid >> 5;
    int base = blockIdx.x * 1024 + tid * 4;
    int v0 = (base + 0 < NN) ? cnt[base + 0] : 0;
    int v1 = (base + 1 < NN) ? cnt[base + 1] : 0;
    int v2 = (base + 2 < NN) ? cnt[base + 2] : 0;
    int v3 = (base + 3 < NN) ? cnt[base + 3] : 0;
    int s = v0 + v1 + v2 + v3;
    int x = s;
#pragma unroll
    for (int o = 1; o < 32; o <<= 1) {
        int y = __shfl_up_sync(0xffffffffu, x, o);
        if (lane >= o) x += y;
    }
    if (lane == 31) wsum[w] = x;
    __syncthreads();
    if (tid == 0) {
        int r = 0;
#pragma unroll
        for (int j = 0; j < 8; j++) { int t = wsum[j]; wsum[j] = r; r += t; }
        bsum[blockIdx.x] = r;
    }
    __syncthreads();
    int ex = wsum[w] + x - s;
    if (base + 0 < NN) off[base + 0] = ex;
    if (base + 1 < NN) off[base + 1] = ex + v0;
    if (base + 2 < NN) off[base + 2] = ex + v0 + v1;
    if (base + 3 < NN) off[base + 3] = ex + v0 + v1 + v2;
}

__global__ __launch_bounds__(256) void k_scan2(int* __restrict__ bsum, int nb) {
    __shared__ int sm[256];
    int tid = threadIdx.x;
    int v = (tid < nb) ? bsum[tid] : 0;
    sm[tid] = v;
    __syncthreads();
#pragma unroll
    for (int o = 1; o < 256; o <<= 1) {
        int t = (tid >= o) ? sm[tid - o] : 0;
        __syncthreads();
        sm[tid] += t;
        __syncthreads();
    }
    if (tid < nb) bsum[tid] = sm[tid] - v;   // exclusive
}

__global__ __launch_bounds__(256) void k_scan3(int* __restrict__ off,
                                               const int* __restrict__ bsum) {
    int add = bsum[blockIdx.x];
    int base = blockIdx.x * 1024 + threadIdx.x * 4;
#pragma unroll
    for (int i = 0; i < 4; i++)
        if (base + i < NN) off[base + i] += add;
}

// ---------------- CSR placement with per-edge norms ----------------
__global__ __launch_bounds__(256) void k_place(const int* __restrict__ ei) {
    int e = blockIdx.x * 256 + threadIdx.x;
    if (e >= NE) return;
    int a = __ldg(ei + e);
    int b = __ldg(ei + NE + e);
    float nf = __ldg(&g_disf[a]) * __ldg(&g_disf[b]);
    float nr = __ldg(&g_disr[b]) * __ldg(&g_disr[a]);
    int pf = g_offF[b] + atomicAdd(&g_fillF[b], 1);
    g_csrF[pf] = make_int2(a, __float_as_int(nf));
    int pr = g_offR[a] + atomicAdd(&g_fillR[a], 1);
    g_csrR[pr] = make_int2(b, __float_as_int(nr));
}

// ---------------- encoder stage 1: tmp = leaky(x @ W1 + b1) ----------------
template<int KIN, int KOUT, int NPB>
__global__ __launch_bounds__(256) void k_encA(
    const float* __restrict__ x, const float* __restrict__ W,
    const float* __restrict__ bias, float* __restrict__ tmp, int nNodes)
{
    __shared__ float xs[NPB * KIN];
    int tid = threadIdx.x;
    int base = blockIdx.x * NPB;
    const int NSUB = 256 / KOUT;
#pragma unroll
    for (int i = 0; i < (NPB * KIN + 255) / 256; i++) {
        int idx = tid + i * 256;
        if (idx < NPB * KIN) {
            size_t gidx = (size_t)base * KIN + idx;
            size_t mx = (size_t)nNodes * KIN - 1;
            xs[idx] = x[gidx <= mx ? gidx : mx];
        }
    }
    int j = tid & (KOUT - 1);
    int nsub = tid / KOUT;
    float wcol[KIN];
#pragma unroll
    for (int k = 0; k < KIN; k++) wcol[k] = W[k * KOUT + j];
    float bj = bias[j];
    __syncthreads();
#pragma unroll
    for (int t = 0; t < NPB / NSUB; t++) {
        int n = nsub + t * NSUB;
        float a = bj;
#pragma unroll
        for (int k4 = 0; k4 < KIN; k4 += 4) {
            float4 xv = *(const float4*)&xs[n * KIN + k4];
            a += xv.x * wcol[k4] + xv.y * wcol[k4 + 1]
               + xv.z * wcol[k4 + 2] + xv.w * wcol[k4 + 3];
        }
        if (base + n < nNodes)
            tmp[(size_t)(base + n) * KOUT + j] = leaky(a);
    }
}

// ---------------- register-tiled GEMM: dst = act(src @ W + b) ----------------
// 64 nodes/block, 128 threads. Thread: 8 nodes (packed pairs) x 4 outputs.
template<int KTOT, bool LEAKY>
__global__ __launch_bounds__(128) void k_mm(
    const float* __restrict__ src, int srcStride, int srcOff, int srcBase,
    const float* __restrict__ W, const float* __restrict__ bias,
    float* __restrict__ dst, int dstStride, int dstOff, int dstBase,
    int nNodes)
{
    __shared__ float hs[64 * 68];   // hs[kLocal*68 + nLocal] (transposed, padded)
    __shared__ float ws[64 * 64];   // W chunk [kLocal][out]
    int tid = threadIdx.x;
    int tb = blockIdx.x * 64;
    int tx = tid & 15, ty = tid >> 4;
    int bn = ty * 8;
    unsigned long long acc[4][4];
#pragma unroll
    for (int a = 0; a < 4; a++)
#pragma unroll
        for (int b = 0; b < 4; b++) acc[a][b] = 0ull;

    int c = tid & 63, r = tid >> 6;
    for (int kc = 0; kc < KTOT; kc += 64) {
        if (kc) __syncthreads();
#pragma unroll
        for (int i = 0; i < 32; i++)
            ws[tid + i * 128] = W[kc * 64 + tid + i * 128];
#pragma unroll
        for (int i = 0; i < 32; i++) {
            int nl = i * 2 + r;
            int g = tb + nl; if (g >= nNodes) g = nNodes - 1;
            hs[c * 68 + nl] = src[(size_t)(srcBase + g) * srcStride + srcOff + kc + c];
        }
        __syncthreads();
#pragma unroll 4
        for (int k = 0; k < 64; k++) {
            float4 wf = *(const float4*)&ws[k * 64 + tx * 4];
            unsigned long long dw0 = dup64(wf.x);
            unsigned long long dw1 = dup64(wf.y);
            unsigned long long dw2 = dup64(wf.z);
            unsigned long long dw3 = dup64(wf.w);
            ulonglong2 hA = *(const ulonglong2*)&hs[k * 68 + bn];
            ulonglong2 hB = *(const ulonglong2*)&hs[k * 68 + bn + 4];
            fma2(acc[0][0], hA.x, dw0); fma2(acc[0][1], hA.x, dw1);
            fma2(acc[0][2], hA.x, dw2); fma2(acc[0][3], hA.x, dw3);
            fma2(acc[1][0], hA.y, dw0); fma2(acc[1][1], hA.y, dw1);
            fma2(acc[1][2], hA.y, dw2); fma2(acc[1][3], hA.y, dw3);
            fma2(acc[2][0], hB.x, dw0); fma2(acc[2][1], hB.x, dw1);
            fma2(acc[2][2], hB.x, dw2); fma2(acc[2][3], hB.x, dw3);
            fma2(acc[3][0], hB.y, dw0); fma2(acc[3][1], hB.y, dw1);
            fma2(acc[3][2], hB.y, dw2); fma2(acc[3][3], hB.y, dw3);
        }
    }
    float4 bv = *(const float4*)&bias[tx * 4];
#pragma unroll
    for (int np = 0; np < 4; np++) {
        int n0 = tb + bn + np * 2;
        float2 v0 = up64(acc[np][0]);
        float2 v1 = up64(acc[np][1]);
        float2 v2 = up64(acc[np][2]);
        float2 v3 = up64(acc[np][3]);
        float4 o0 = make_float4(v0.x + bv.x, v1.x + bv.y, v2.x + bv.z, v3.x + bv.w);
        float4 o1 = make_float4(v0.y + bv.x, v1.y + bv.y, v2.y + bv.z, v3.y + bv.w);
        if (LEAKY) {
            o0 = make_float4(leaky(o0.x), leaky(o0.y), leaky(o0.z), leaky(o0.w));
            o1 = make_float4(leaky(o1.x), leaky(o1.y), leaky(o1.z), leaky(o1.w));
        }
        if (n0 < nNodes)
            *(float4*)&dst[(size_t)(dstBase + n0) * dstStride + dstOff + tx * 4] = o0;
        if (n0 + 1 < nNodes)
            *(float4*)&dst[(size_t)(dstBase + n0 + 1) * dstStride + dstOff + tx * 4] = o1;
    }
}

// ---------------- forward pull aggregation: acc[n] = sum norm*relu(xf[src]) ----------------
__global__ __launch_bounds__(256) void k_aggF() {
    int n = blockIdx.x * 8 + (threadIdx.x >> 5);
    int lane = threadIdx.x & 31;
    int d = lane * 2;
    int beg = g_offF[n];
    int deg = g_cntr[n];          // fwd buckets are keyed by col -> cntr
    const int2* cs = g_csrF + beg;
    float2 acc = make_float2(0.f, 0.f);
    int i = 0;
    for (; i + 2 <= deg; i += 2) {
        int2 e0 = __ldg(cs + i), e1 = __ldg(cs + i + 1);
        float2 v0 = *(const float2*)&g_xf[(size_t)e0.x * 64 + d];
        float2 v1 = *(const float2*)&g_xf[(size_t)e1.x * 64 + d];
        float n0 = __int_as_float(e0.y), n1 = __int_as_float(e1.y);
        acc.x += fmaxf(v0.x, 0.f) * n0 + fmaxf(v1.x, 0.f) * n1;
        acc.y += fmaxf(v0.y, 0.f) * n0 + fmaxf(v1.y, 0.f) * n1;
    }
    if (i < deg) {
        int2 e0 = __ldg(cs + i);
        float2 v0 = *(const float2*)&g_xf[(size_t)e0.x * 64 + d];
        float n0 = __int_as_float(e0.y);
        acc.x += fmaxf(v0.x, 0.f) * n0;
        acc.y += fmaxf(v0.y, 0.f) * n0;
    }
    *(float2*)&g_acc[(size_t)n * 64 + d] = acc;
}

// ---------------- reverse pull aggregation + self terms + LayerNorm + leaky ----------------
__global__ __launch_bounds__(256) void k_aggR(
    const float* __restrict__ rootf, const float* __restrict__ rootr,
    const float* __restrict__ lg, const float* __restrict__ lb,
    float* __restrict__ out, int off)
{
    int n = blockIdx.x * 8 + (threadIdx.x >> 5);
    int lane = threadIdx.x & 31;
    int d = lane * 2;
    int beg = g_offR[n];
    int deg = g_cntf[n];          // rev buckets keyed by row -> cntf
    const int2* cs = g_csrR + beg;
    float2 acc = make_float2(0.f, 0.f);
    int i = 0;
    for (; i + 2 <= deg; i += 2) {
        int2 e0 = __ldg(cs + i), e1 = __ldg(cs + i + 1);
        float2 v0 = *(const float2*)&g_xr[(size_t)e0.x * 64 + d];
        float2 v1 = *(const float2*)&g_xr[(size_t)e1.x * 64 + d];
        float n0 = __int_as_float(e0.y), n1 = __int_as_float(e1.y);
        acc.x += fmaxf(v0.x, 0.f) * n0 + fmaxf(v1.x, 0.f) * n1;
        acc.y += fmaxf(v0.y, 0.f) * n0 + fmaxf(v1.y, 0.f) * n1;
    }
    if (i < deg) {
        int2 e0 = __ldg(cs + i);
        float2 v0 = *(const float2*)&g_xr[(size_t)e0.x * 64 + d];
        float n0 = __int_as_float(e0.y);
        acc.x += fmaxf(v0.x, 0.f) * n0;
        acc.y += fmaxf(v0.y, 0.f) * n0;
    }
    size_t o64 = (size_t)n * 64 + d;
    float2 f  = *(const float2*)&g_acc[o64];
    float2 fx = *(const float2*)&g_xf[o64];
    float2 rx = *(const float2*)&g_xr[o64];
    float idf = g_idegf[n], idr = g_idegr[n];
    float s0 = acc.x + f.x + fmaxf(fx.x + rootf[d], 0.f) * idf
                           + fmaxf(rx.x + rootr[d], 0.f) * idr;
    float s1 = acc.y + f.y + fmaxf(fx.y + rootf[d + 1], 0.f) * idf
                           + fmaxf(rx.y + rootr[d + 1], 0.f) * idr;
    float sum = s0 + s1;
#pragma unroll
    for (int o = 16; o > 0; o >>= 1) sum += __shfl_xor_sync(0xffffffffu, sum, o);
    float m = sum * (1.0f / 64.0f);
    float d0 = s0 - m, d1 = s1 - m;
    float sq = d0 * d0 + d1 * d1;
#pragma unroll
    for (int o = 16; o > 0; o >>= 1) sq += __shfl_xor_sync(0xffffffffu, sq, o);
    float inv = rsqrtf(sq * (1.0f / 64.0f) + 1e-5f);
    float o0 = leaky(d0 * inv * lg[d] + lb[d]);
    float o1 = leaky(d1 * inv * lg[d + 1] + lb[d + 1]);
    *(float2*)&out[(size_t)n * 256 + off + d] = make_float2(o0, o1);
}

// ---------------- launch ----------------
extern "C" void kernel_launch(void* const* d_in, const int* in_sizes, int n_in,
                              void* d_out, int out_size) {
    const float* x     = (const float*)d_in[0];
    const float* xnet  = (const float*)d_in[1];
    const int*   ei    = (const int*)  d_in[2];
    const float* e1W   = (const float*)d_in[3];
    const float* e1b   = (const float*)d_in[4];
    const float* e2W   = (const float*)d_in[5];
    const float* e2b   = (const float*)d_in[6];
    const float* n1W   = (const float*)d_in[7];
    const float* n1b   = (const float*)d_in[8];
    const float* n2W   = (const float*)d_in[9];
    const float* n2b   = (const float*)d_in[10];
    const float* convW = (const float*)d_in[11];
    const float* convb = (const float*)d_in[12];
    const float* convr = (const float*)d_in[13];
    const float* reW   = (const float*)d_in[14];
    const float* reb   = (const float*)d_in[15];
    const float* rer   = (const float*)d_in[16];
    const float* lng   = (const float*)d_in[17];
    const float* lnb   = (const float*)d_in[18];
    float* out = (float*)d_out;

    void *pcf, *pcr, *pff, *pfr, *poF, *poR, *pbF, *pbR, *pxf, *pxr, *ptmp, *ptmpn;
    cudaGetSymbolAddress(&pcf, g_cntf);
    cudaGetSymbolAddress(&pcr, g_cntr);
    cudaGetSymbolAddress(&pff, g_fillF);
    cudaGetSymbolAddress(&pfr, g_fillR);
    cudaGetSymbolAddress(&poF, g_offF);
    cudaGetSymbolAddress(&poR, g_offR);
    cudaGetSymbolAddress(&pbF, g_bsF);
    cudaGetSymbolAddress(&pbR, g_bsR);
    cudaGetSymbolAddress(&pxf, g_xf);
    cudaGetSymbolAddress(&pxr, g_xr);
    cudaGetSymbolAddress(&ptmp, g_tmp);
    cudaGetSymbolAddress(&ptmpn, g_tmpn);

    // side stream + events, created eagerly on the first (uncaptured) call
    static cudaStream_t s2 = []() {
        cudaStream_t s; cudaStreamCreateWithFlags(&s, cudaStreamNonBlocking); return s;
    }();
    static cudaEvent_t evF = []() {
        cudaEvent_t e; cudaEventCreateWithFlags(&e, cudaEventDisableTiming); return e;
    }();
    static cudaEvent_t evJ = []() {
        cudaEvent_t e; cudaEventCreateWithFlags(&e, cudaEventDisableTiming); return e;
    }();

    cudaEventRecord(evF, 0);
    cudaStreamWaitEvent(s2, evF, 0);

    // ---- branch B (side stream): CSR build ----
    cudaMemsetAsync(pcf, 0, NN * sizeof(int), s2);
    cudaMemsetAsync(pcr, 0, NN * sizeof(int), s2);
    cudaMemsetAsync(pff, 0, NN * sizeof(int), s2);
    cudaMemsetAsync(pfr, 0, NN * sizeof(int), s2);
    k_count<<<(NE + 255) / 256, 256, 0, s2>>>(ei);
    k_deg<<<(NN + 255) / 256, 256, 0, s2>>>();
    k_scan1<<<NSCANB, 256, 0, s2>>>((const int*)pcr, (int*)poF, (int*)pbF);
    k_scan1<<<NSCANB, 256, 0, s2>>>((const int*)pcf, (int*)poR, (int*)pbR);
    k_scan2<<<1, 256, 0, s2>>>((int*)pbF, NSCANB);
    k_scan2<<<1, 256, 0, s2>>>((int*)pbR, NSCANB);
    k_scan3<<<NSCANB, 256, 0, s2>>>((int*)poF, (const int*)pbF);
    k_scan3<<<NSCANB, 256, 0, s2>>>((int*)poR, (const int*)pbR);
    k_place<<<(NE + 255) / 256, 256, 0, s2>>>(ei);
    cudaEventRecord(evJ, s2);

    // ---- branch A (main stream): encoders ----
    k_encA<16, 128, 32><<<N_INST / 32, 256>>>(x, e1W, e1b, (float*)ptmp, N_INST);
    k_mm<128, true><<<(N_INST + 63) / 64, 128>>>(
        (const float*)ptmp, 128, 0, 0, e2W, e2b, out, 256, 0, 0, N_INST);
    k_encA<8, 64, 32><<<(N_NETN + 31) / 32, 256>>>(xnet, n1W, n1b, (float*)ptmpn, N_NETN);
    k_mm<64, true><<<(N_NETN + 63) / 64, 128>>>(
        (const float*)ptmpn, 64, 0, 0, n2W, n2b, out, 256, 0, N_INST, N_NETN);

    cudaStreamWaitEvent(0, evJ, 0);

    // ---- layers ----
    for (int l = 0; l < 3; l++) {
        k_mm<64, false><<<(NN + 63) / 64, 128>>>(
            out, 256, l * 64, 0, convW + l * 4096, convb + l * 64,
            (float*)pxf, 64, 0, 0, NN);
        k_mm<64, false><<<(NN + 63) / 64, 128>>>(
            out, 256, l * 64, 0, reW + l * 4096, reb + l * 64,
            (float*)pxr, 64, 0, 0, NN);
        k_aggF<<<NN / 8, 256>>>();
        k_aggR<<<NN / 8, 256>>>(convr + l * 64, rer + l * 64,
                                lng + l * 64, lnb + l * 64,
                                out, (l + 1) * 64);
    }
}

// round 4
// speedup vs baseline: 1.4334x; 1.0050x over previous
#include <cuda_runtime.h>
#include <cuda_fp16.h>

#define N_INST 200000
#define N_NETN 50000
#define NN     250000
#define NE     2000000
#define NSCANB 245   // ceil(250000/1024)

// ---------------- device scratch (no runtime allocation allowed) ----------------
__device__ float   g_xf[(size_t)NN * 64];     // x_f = h @ Wf + bf (fp32, self term)
__device__ float   g_xr[(size_t)NN * 64];     // x_r = h @ Wr + br
__device__ __half2 g_yf[(size_t)NN * 32];     // relu(x_f) fp16 (gather payload)
__device__ __half2 g_yr[(size_t)NN * 32];     // relu(x_r) fp16
__device__ float   g_acc[(size_t)NN * 64];    // forward aggregation result
__device__ float   g_tmp[(size_t)N_INST * 128]; // encoder hidden (inst)
__device__ float   g_tmpn[(size_t)N_NETN * 64]; // encoder hidden (net)
__device__ float   g_disf[NN], g_disr[NN];    // deg^-1/2
__device__ float   g_idegf[NN], g_idegr[NN];  // deg^-1
__device__ int     g_cntf[NN], g_cntr[NN];    // edge counts (row / col)
__device__ int     g_offF[NN], g_offR[NN];    // CSR bucket starts
__device__ int     g_fillF[NN], g_fillR[NN];
__device__ int     g_bsF[256], g_bsR[256];    // scan block sums
__device__ int2    g_csrF[NE];                // (src, norm) bucketed by col
__device__ int2    g_csrR[NE];                // (src, norm) bucketed by row

// ---------------- helpers ----------------
__device__ __forceinline__ float leaky(float v) { return fmaxf(v, 0.1f * v); }

__device__ __forceinline__ unsigned long long dup64(float a) {
    unsigned long long r;
    asm("mov.b64 %0, {%1, %1};" : "=l"(r) : "f"(a));
    return r;
}
__device__ __forceinline__ float2 up64(unsigned long long v) {
    float2 r;
    asm("mov.b64 {%0, %1}, %2;" : "=f"(r.x), "=f"(r.y) : "l"(v));
    return r;
}
__device__ __forceinline__ void fma2(unsigned long long& d,
                                     unsigned long long a,
                                     unsigned long long b) {
    asm("fma.rn.f32x2 %0, %1, %2, %0;" : "+l"(d) : "l"(a), "l"(b));
}

// ---------------- degree counting ----------------
__global__ __launch_bounds__(256) void k_count(const int* __restrict__ ei) {
    int e = blockIdx.x * 256 + threadIdx.x;
    if (e >= NE) return;
    atomicAdd(&g_cntf[ei[e]], 1);
    atomicAdd(&g_cntr[ei[NE + e]], 1);
}

__global__ __launch_bounds__(256) void k_deg() {
    int n = blockIdx.x * 256 + threadIdx.x;
    if (n >= NN) return;
    float df = (float)g_cntf[n] + 1.0f;
    float dr = (float)g_cntr[n] + 1.0f;
    g_disf[n] = rsqrtf(df);
    g_disr[n] = rsqrtf(dr);
    g_idegf[n] = 1.0f / df;
    g_idegr[n] = 1.0f / dr;
}

// ---------------- exclusive scan ----------------
__global__ __launch_bounds__(256) void k_scan1(const int* __restrict__ cnt,
                                               int* __restrict__ off,
                                               int* __restrict__ bsum) {
    __shared__ int wsum[8];
    int tid = threadIdx.x, lane = tid & 31, w = tid >> 5;
    int base = blockIdx.x * 1024 + tid * 4;
    int v0 = (base + 0 < NN) ? cnt[base + 0] : 0;
    int v1 = (base + 1 < NN) ? cnt[base + 1] : 0;
    int v2 = (base + 2 < NN) ? cnt[base + 2] : 0;
    int v3 = (base + 3 < NN) ? cnt[base + 3] : 0;
    int s = v0 + v1 + v2 + v3;
    int x = s;
#pragma unroll
    for (int o = 1; o < 32; o <<= 1) {
        int y = __shfl_up_sync(0xffffffffu, x, o);
        if (lane >= o) x += y;
    }
    if (lane == 31) wsum[w] = x;
    __syncthreads();
    if (tid == 0) {
        int r = 0;
#pragma unroll
        for (int j = 0; j < 8; j++) { int t = wsum[j]; wsum[j] = r; r += t; }
        bsum[blockIdx.x] = r;
    }
    __syncthreads();
    int ex = wsum[w] + x - s;
    if (base + 0 < NN) off[base + 0] = ex;
    if (base + 1 < NN) off[base + 1] = ex + v0;
    if (base + 2 < NN) off[base + 2] = ex + v0 + v1;
    if (base + 3 < NN) off[base + 3] = ex + v0 + v1 + v2;
}

__global__ __launch_bounds__(256) void k_scan2(int* __restrict__ bsum, int nb) {
    __shared__ int sm[256];
    int tid = threadIdx.x;
    int v = (tid < nb) ? bsum[tid] : 0;
    sm[tid] = v;
    __syncthreads();
#pragma unroll
    for (int o = 1; o < 256; o <<= 1) {
        int t = (tid >= o) ? sm[tid - o] : 0;
        __syncthreads();
        sm[tid] += t;
        __syncthreads();
    }
    if (tid < nb) bsum[tid] = sm[tid] - v;
}

__global__ __launch_bounds__(256) void k_scan3(int* __restrict__ off,
                                               const int* __restrict__ bsum) {
    int add = bsum[blockIdx.x];
    int base = blockIdx.x * 1024 + threadIdx.x * 4;
#pragma unroll
    for (int i = 0; i < 4; i++)
        if (base + i < NN) off[base + i] += add;
}

// ---------------- CSR placement with per-edge norms ----------------
__global__ __launch_bounds__(256) void k_place(const int* __restrict__ ei) {
    int e = blockIdx.x * 256 + threadIdx.x;
    if (e >= NE) return;
    int a = __ldg(ei + e);
    int b = __ldg(ei + NE + e);
    float nf = __ldg(&g_disf[a]) * __ldg(&g_disf[b]);
    float nr = __ldg(&g_disr[b]) * __ldg(&g_disr[a]);
    int pf = g_offF[b] + atomicAdd(&g_fillF[b], 1);
    g_csrF[pf] = make_int2(a, __float_as_int(nf));
    int pr = g_offR[a] + atomicAdd(&g_fillR[a], 1);
    g_csrR[pr] = make_int2(b, __float_as_int(nr));
}

// ---------------- encoder stage 1 ----------------
template<int KIN, int KOUT, int NPB>
__global__ __launch_bounds__(256) void k_encA(
    const float* __restrict__ x, const float* __restrict__ W,
    const float* __restrict__ bias, float* __restrict__ tmp, int nNodes)
{
    __shared__ float xs[NPB * KIN];
    int tid = threadIdx.x;
    int base = blockIdx.x * NPB;
    const int NSUB = 256 / KOUT;
#pragma unroll
    for (int i = 0; i < (NPB * KIN + 255) / 256; i++) {
        int idx = tid + i * 256;
        if (idx < NPB * KIN) {
            size_t gidx = (size_t)base * KIN + idx;
            size_t mx = (size_t)nNodes * KIN - 1;
            xs[idx] = x[gidx <= mx ? gidx : mx];
        }
    }
    int j = tid & (KOUT - 1);
    int nsub = tid / KOUT;
    float wcol[KIN];
#pragma unroll
    for (int k = 0; k < KIN; k++) wcol[k] = W[k * KOUT + j];
    float bj = bias[j];
    __syncthreads();
#pragma unroll
    for (int t = 0; t < NPB / NSUB; t++) {
        int n = nsub + t * NSUB;
        float a = bj;
#pragma unroll
        for (int k4 = 0; k4 < KIN; k4 += 4) {
            float4 xv = *(const float4*)&xs[n * KIN + k4];
            a += xv.x * wcol[k4] + xv.y * wcol[k4 + 1]
               + xv.z * wcol[k4 + 2] + xv.w * wcol[k4 + 3];
        }
        if (base + n < nNodes)
            tmp[(size_t)(base + n) * KOUT + j] = leaky(a);
    }
}

// ---------------- register-tiled GEMM: dst = act(src @ W + b) ----------------
// Optional WRELU epilogue: yout[n][f/2] = half2(relu(val))
template<int KTOT, bool LEAKY, bool WRELU>
__global__ __launch_bounds__(128) void k_mm(
    const float* __restrict__ src, int srcStride, int srcOff, int srcBase,
    const float* __restrict__ W, const float* __restrict__ bias,
    float* __restrict__ dst, int dstStride, int dstOff, int dstBase,
    __half2* __restrict__ yout, int nNodes)
{
    __shared__ float hs[64 * 68];
    __shared__ float ws[64 * 64];
    int tid = threadIdx.x;
    int tb = blockIdx.x * 64;
    int tx = tid & 15, ty = tid >> 4;
    int bn = ty * 8;
    unsigned long long acc[4][4];
#pragma unroll
    for (int a = 0; a < 4; a++)
#pragma unroll
        for (int b = 0; b < 4; b++) acc[a][b] = 0ull;

    int c = tid & 63, r = tid >> 6;
    for (int kc = 0; kc < KTOT; kc += 64) {
        if (kc) __syncthreads();
#pragma unroll
        for (int i = 0; i < 32; i++)
            ws[tid + i * 128] = W[kc * 64 + tid + i * 128];
#pragma unroll
        for (int i = 0; i < 32; i++) {
            int nl = i * 2 + r;
            int g = tb + nl; if (g >= nNodes) g = nNodes - 1;
            hs[c * 68 + nl] = src[(size_t)(srcBase + g) * srcStride + srcOff + kc + c];
        }
        __syncthreads();
#pragma unroll 4
        for (int k = 0; k < 64; k++) {
            float4 wf = *(const float4*)&ws[k * 64 + tx * 4];
            unsigned long long dw0 = dup64(wf.x);
            unsigned long long dw1 = dup64(wf.y);
            unsigned long long dw2 = dup64(wf.z);
            unsigned long long dw3 = dup64(wf.w);
            ulonglong2 hA = *(const ulonglong2*)&hs[k * 68 + bn];
            ulonglong2 hB = *(const ulonglong2*)&hs[k * 68 + bn + 4];
            fma2(acc[0][0], hA.x, dw0); fma2(acc[0][1], hA.x, dw1);
            fma2(acc[0][2], hA.x, dw2); fma2(acc[0][3], hA.x, dw3);
            fma2(acc[1][0], hA.y, dw0); fma2(acc[1][1], hA.y, dw1);
            fma2(acc[1][2], hA.y, dw2); fma2(acc[1][3], hA.y, dw3);
            fma2(acc[2][0], hB.x, dw0); fma2(acc[2][1], hB.x, dw1);
            fma2(acc[2][2], hB.x, dw2); fma2(acc[2][3], hB.x, dw3);
            fma2(acc[3][0], hB.y, dw0); fma2(acc[3][1], hB.y, dw1);
            fma2(acc[3][2], hB.y, dw2); fma2(acc[3][3], hB.y, dw3);
        }
    }
    float4 bv = *(const float4*)&bias[tx * 4];
#pragma unroll
    for (int np = 0; np < 4; np++) {
        int n0 = tb + bn + np * 2;
        float2 v0 = up64(acc[np][0]);
        float2 v1 = up64(acc[np][1]);
        float2 v2 = up64(acc[np][2]);
        float2 v3 = up64(acc[np][3]);
        float4 o0 = make_float4(v0.x + bv.x, v1.x + bv.y, v2.x + bv.z, v3.x + bv.w);
        float4 o1 = make_float4(v0.y + bv.x, v1.y + bv.y, v2.y + bv.z, v3.y + bv.w);
        if (LEAKY) {
            o0 = make_float4(leaky(o0.x), leaky(o0.y), leaky(o0.z), leaky(o0.w));
            o1 = make_float4(leaky(o1.x), leaky(o1.y), leaky(o1.z), leaky(o1.w));
        }
        if (n0 < nNodes) {
            *(float4*)&dst[(size_t)(dstBase + n0) * dstStride + dstOff + tx * 4] = o0;
            if (WRELU) {
                __half2 h0 = __float22half2_rn(make_float2(fmaxf(o0.x, 0.f), fmaxf(o0.y, 0.f)));
                __half2 h1 = __float22half2_rn(make_float2(fmaxf(o0.z, 0.f), fmaxf(o0.w, 0.f)));
                uint2 pk = make_uint2(*(unsigned*)&h0, *(unsigned*)&h1);
                *(uint2*)&yout[(size_t)n0 * 32 + tx * 2] = pk;
            }
        }
        if (n0 + 1 < nNodes) {
            *(float4*)&dst[(size_t)(dstBase + n0 + 1) * dstStride + dstOff + tx * 4] = o1;
            if (WRELU) {
                __half2 h0 = __float22half2_rn(make_float2(fmaxf(o1.x, 0.f), fmaxf(o1.y, 0.f)));
                __half2 h1 = __float22half2_rn(make_float2(fmaxf(o1.z, 0.f), fmaxf(o1.w, 0.f)));
                uint2 pk = make_uint2(*(unsigned*)&h0, *(unsigned*)&h1);
                *(uint2*)&yout[(size_t)(n0 + 1) * 32 + tx * 2] = pk;
            }
        }
    }
}

// ---------------- forward pull aggregation (fp16 payload) ----------------
__global__ __launch_bounds__(256) void k_aggF() {
    int n = blockIdx.x * 8 + (threadIdx.x >> 5);
    int lane = threadIdx.x & 31;
    int beg = g_offF[n];
    int deg = g_cntr[n];
    const int2* cs = g_csrF + beg;
    const __half2* Y = g_yf;
    float2 acc = make_float2(0.f, 0.f);
    int i = 0;
    for (; i + 4 <= deg; i += 4) {
        int2 e0 = __ldg(cs + i), e1 = __ldg(cs + i + 1);
        int2 e2 = __ldg(cs + i + 2), e3 = __ldg(cs + i + 3);
        float2 v0 = __half22float2(__ldg(Y + (size_t)e0.x * 32 + lane));
        float2 v1 = __half22float2(__ldg(Y + (size_t)e1.x * 32 + lane));
        float2 v2 = __half22float2(__ldg(Y + (size_t)e2.x * 32 + lane));
        float2 v3 = __half22float2(__ldg(Y + (size_t)e3.x * 32 + lane));
        float n0 = __int_as_float(e0.y), n1 = __int_as_float(e1.y);
        float n2 = __int_as_float(e2.y), n3 = __int_as_float(e3.y);
        acc.x += v0.x * n0 + v1.x * n1 + v2.x * n2 + v3.x * n3;
        acc.y += v0.y * n0 + v1.y * n1 + v2.y * n2 + v3.y * n3;
    }
    for (; i < deg; i++) {
        int2 e0 = __ldg(cs + i);
        float2 v0 = __half22float2(__ldg(Y + (size_t)e0.x * 32 + lane));
        float n0 = __int_as_float(e0.y);
        acc.x += v0.x * n0;
        acc.y += v0.y * n0;
    }
    *(float2*)&g_acc[(size_t)n * 64 + lane * 2] = acc;
}

// ---------------- reverse pull aggregation + self terms + LayerNorm + leaky ----------------
__global__ __launch_bounds__(256) void k_aggR(
    const float* __restrict__ rootf, const float* __restrict__ rootr,
    const float* __restrict__ lg, const float* __restrict__ lb,
    float* __restrict__ out, int off)
{
    int n = blockIdx.x * 8 + (threadIdx.x >> 5);
    int lane = threadIdx.x & 31;
    int d = lane * 2;
    int beg = g_offR[n];
    int deg = g_cntf[n];
    const int2* cs = g_csrR + beg;
    const __half2* Y = g_yr;
    float2 acc = make_float2(0.f, 0.f);
    int i = 0;
    for (; i + 4 <= deg; i += 4) {
        int2 e0 = __ldg(cs + i), e1 = __ldg(cs + i + 1);
        int2 e2 = __ldg(cs + i + 2), e3 = __ldg(cs + i + 3);
        float2 v0 = __half22float2(__ldg(Y + (size_t)e0.x * 32 + lane));
        float2 v1 = __half22float2(__ldg(Y + (size_t)e1.x * 32 + lane));
        float2 v2 = __half22float2(__ldg(Y + (size_t)e2.x * 32 + lane));
        float2 v3 = __half22float2(__ldg(Y + (size_t)e3.x * 32 + lane));
        float n0 = __int_as_float(e0.y), n1 = __int_as_float(e1.y);
        float n2 = __int_as_float(e2.y), n3 = __int_as_float(e3.y);
        acc.x += v0.x * n0 + v1.x * n1 + v2.x * n2 + v3.x * n3;
        acc.y += v0.y * n0 + v1.y * n1 + v2.y * n2 + v3.y * n3;
    }
    for (; i < deg; i++) {
        int2 e0 = __ldg(cs + i);
        float2 v0 = __half22float2(__ldg(Y + (size_t)e0.x * 32 + lane));
        float n0 = __int_as_float(e0.y);
        acc.x += v0.x * n0;
        acc.y += v0.y * n0;
    }
    size_t o64 = (size_t)n * 64 + d;
    float2 f  = *(const float2*)&g_acc[o64];
    float2 fx = *(const float2*)&g_xf[o64];
    float2 rx = *(const float2*)&g_xr[o64];
    float idf = g_idegf[n], idr = g_idegr[n];
    float s0 = acc.x + f.x + fmaxf(fx.x + rootf[d], 0.f) * idf
                           + fmaxf(rx.x + rootr[d], 0.f) * idr;
    float s1 = acc.y + f.y + fmaxf(fx.y + rootf[d + 1], 0.f) * idf
                           + fmaxf(rx.y + rootr[d + 1], 0.f) * idr;
    float sum = s0 + s1;
#pragma unroll
    for (int o = 16; o > 0; o >>= 1) sum += __shfl_xor_sync(0xffffffffu, sum, o);
    float m = sum * (1.0f / 64.0f);
    float d0 = s0 - m, d1 = s1 - m;
    float sq = d0 * d0 + d1 * d1;
#pragma unroll
    for (int o = 16; o > 0; o >>= 1) sq += __shfl_xor_sync(0xffffffffu, sq, o);
    float inv = rsqrtf(sq * (1.0f / 64.0f) + 1e-5f);
    float o0 = leaky(d0 * inv * lg[d] + lb[d]);
    float o1 = leaky(d1 * inv * lg[d + 1] + lb[d + 1]);
    *(float2*)&out[(size_t)n * 256 + off + d] = make_float2(o0, o1);
}

// ---------------- launch ----------------
extern "C" void kernel_launch(void* const* d_in, const int* in_sizes, int n_in,
                              void* d_out, int out_size) {
    const float* x     = (const float*)d_in[0];
    const float* xnet  = (const float*)d_in[1];
    const int*   ei    = (const int*)  d_in[2];
    const float* e1W   = (const float*)d_in[3];
    const float* e1b   = (const float*)d_in[4];
    const float* e2W   = (const float*)d_in[5];
    const float* e2b   = (const float*)d_in[6];
    const float* n1W   = (const float*)d_in[7];
    const float* n1b   = (const float*)d_in[8];
    const float* n2W   = (const float*)d_in[9];
    const float* n2b   = (const float*)d_in[10];
    const float* convW = (const float*)d_in[11];
    const float* convb = (const float*)d_in[12];
    const float* convr = (const float*)d_in[13];
    const float* reW   = (const float*)d_in[14];
    const float* reb   = (const float*)d_in[15];
    const float* rer   = (const float*)d_in[16];
    const float* lng   = (const float*)d_in[17];
    const float* lnb   = (const float*)d_in[18];
    float* out = (float*)d_out;

    void *pcf, *pcr, *pff, *pfr, *poF, *poR, *pbF, *pbR, *pxf, *pxr, *pyf, *pyr, *ptmp, *ptmpn;
    cudaGetSymbolAddress(&pcf, g_cntf);
    cudaGetSymbolAddress(&pcr, g_cntr);
    cudaGetSymbolAddress(&pff, g_fillF);
    cudaGetSymbolAddress(&pfr, g_fillR);
    cudaGetSymbolAddress(&poF, g_offF);
    cudaGetSymbolAddress(&poR, g_offR);
    cudaGetSymbolAddress(&pbF, g_bsF);
    cudaGetSymbolAddress(&pbR, g_bsR);
    cudaGetSymbolAddress(&pxf, g_xf);
    cudaGetSymbolAddress(&pxr, g_xr);
    cudaGetSymbolAddress(&pyf, g_yf);
    cudaGetSymbolAddress(&pyr, g_yr);
    cudaGetSymbolAddress(&ptmp, g_tmp);
    cudaGetSymbolAddress(&ptmpn, g_tmpn);

    static cudaStream_t s2 = []() {
        cudaStream_t s; cudaStreamCreateWithFlags(&s, cudaStreamNonBlocking); return s;
    }();
    static cudaEvent_t evF = []() {
        cudaEvent_t e; cudaEventCreateWithFlags(&e, cudaEventDisableTiming); return e;
    }();
    static cudaEvent_t evJ = []() {
        cudaEvent_t e; cudaEventCreateWithFlags(&e, cudaEventDisableTiming); return e;
    }();
    static cudaEvent_t evA[3] = {[]() { cudaEvent_t e; cudaEventCreateWithFlags(&e, cudaEventDisableTiming); return e; }(),
                                 []() { cudaEvent_t e; cudaEventCreateWithFlags(&e, cudaEventDisableTiming); return e; }(),
                                 []() { cudaEvent_t e; cudaEventCreateWithFlags(&e, cudaEventDisableTiming); return e; }()};
    static cudaEvent_t evM[3] = {[]() { cudaEvent_t e; cudaEventCreateWithFlags(&e, cudaEventDisableTiming); return e; }(),
                                 []() { cudaEvent_t e; cudaEventCreateWithFlags(&e, cudaEventDisableTiming); return e; }(),
                                 []() { cudaEvent_t e; cudaEventCreateWithFlags(&e, cudaEventDisableTiming); return e; }()};

    cudaEventRecord(evF, 0);
    cudaStreamWaitEvent(s2, evF, 0);

    // ---- branch B (side stream): CSR build ----
    cudaMemsetAsync(pcf, 0, NN * sizeof(int), s2);
    cudaMemsetAsync(pcr, 0, NN * sizeof(int), s2);
    cudaMemsetAsync(pff, 0, NN * sizeof(int), s2);
    cudaMemsetAsync(pfr, 0, NN * sizeof(int), s2);
    k_count<<<(NE + 255) / 256, 256, 0, s2>>>(ei);
    k_deg<<<(NN + 255) / 256, 256, 0, s2>>>();
    k_scan1<<<NSCANB, 256, 0, s2>>>((const int*)pcr, (int*)poF, (int*)pbF);
    k_scan1<<<NSCANB, 256, 0, s2>>>((const int*)pcf, (int*)poR, (int*)pbR);
    k_scan2<<<1, 256, 0, s2>>>((int*)pbF, NSCANB);
    k_scan2<<<1, 256, 0, s2>>>((int*)pbR, NSCANB);
    k_scan3<<<NSCANB, 256, 0, s2>>>((int*)poF, (const int*)pbF);
    k_scan3<<<NSCANB, 256, 0, s2>>>((int*)poR, (const int*)pbR);
    k_place<<<(NE + 255) / 256, 256, 0, s2>>>(ei);
    cudaEventRecord(evJ, s2);

    // ---- branch A (main stream): encoders ----
    k_encA<16, 128, 32><<<N_INST / 32, 256>>>(x, e1W, e1b, (float*)ptmp, N_INST);
    k_mm<128, true, false><<<(N_INST + 63) / 64, 128>>>(
        (const float*)ptmp, 128, 0, 0, e2W, e2b, out, 256, 0, 0, nullptr, N_INST);
    k_encA<8, 64, 32><<<(N_NETN + 31) / 32, 256>>>(xnet, n1W, n1b, (float*)ptmpn, N_NETN);
    k_mm<64, true, false><<<(N_NETN + 63) / 64, 128>>>(
        (const float*)ptmpn, 64, 0, 0, n2W, n2b, out, 256, 0, N_INST, nullptr, N_NETN);

    cudaStreamWaitEvent(0, evJ, 0);

    // ---- layers: k_mm_f -> (aggF on s2 || k_mm_r on main) -> aggR ----
    for (int l = 0; l < 3; l++) {
        k_mm<64, false, true><<<(NN + 63) / 64, 128>>>(
            out, 256, l * 64, 0, convW + l * 4096, convb + l * 64,
            (float*)pxf, 64, 0, 0, (__half2*)pyf, NN);
        cudaEventRecord(evA[l], 0);
        cudaStreamWaitEvent(s2, evA[l], 0);
        k_aggF<<<NN / 8, 256, 0, s2>>>();
        cudaEventRecord(evM[l], s2);

        k_mm<64, false, true><<<(NN + 63) / 64, 128>>>(
            out, 256, l * 64, 0, reW + l * 4096, reb + l * 64,
            (float*)pxr, 64, 0, 0, (__half2*)pyr, NN);
        cudaStreamWaitEvent(0, evM[l], 0);
        k_aggR<<<NN / 8, 256>>>(convr + l * 64, rer + l * 64,
                                lng + l * 64, lnb + l * 64,
                                out, (l + 1) * 64);
    }
}

// round 5
// speedup vs baseline: 1.4645x; 1.0218x over previous
#include <cuda_runtime.h>
#include <cuda_fp16.h>

#define N_INST 200000
#define N_NETN 50000
#define NN     250000
#define NE     2000000
#define NSCANB 245   // ceil(250000/1024)

// ---------------- device scratch (no runtime allocation allowed) ----------------
__device__ float   g_xf[(size_t)NN * 64];     // x_f = h @ Wf + bf (fp32, self term)
__device__ float   g_xr[(size_t)NN * 64];     // x_r = h @ Wr + br
__device__ __half2 g_yf[(size_t)NN * 32];     // relu(x_f) fp16 (gather payload)
__device__ __half2 g_yr[(size_t)NN * 32];     // relu(x_r) fp16
__device__ float   g_tmp[(size_t)N_INST * 128]; // encoder hidden (inst)
__device__ float   g_tmpn[(size_t)N_NETN * 64]; // encoder hidden (net)
__device__ float   g_disf[NN], g_disr[NN];    // deg^-1/2
__device__ float   g_idegf[NN], g_idegr[NN];  // deg^-1
__device__ int     g_cntf[NN], g_cntr[NN];    // edge counts (row / col)
__device__ int     g_offF[NN], g_offR[NN];    // CSR bucket starts
__device__ int     g_fillF[NN], g_fillR[NN];
__device__ int     g_bsF[256], g_bsR[256];    // scan block sums
__device__ int2    g_csrF[NE];                // (src, norm) bucketed by col
__device__ int2    g_csrR[NE];                // (src, norm) bucketed by row

// ---------------- helpers ----------------
__device__ __forceinline__ float leaky(float v) { return fmaxf(v, 0.1f * v); }

__device__ __forceinline__ unsigned long long dup64(float a) {
    unsigned long long r;
    asm("mov.b64 %0, {%1, %1};" : "=l"(r) : "f"(a));
    return r;
}
__device__ __forceinline__ float2 up64(unsigned long long v) {
    float2 r;
    asm("mov.b64 {%0, %1}, %2;" : "=f"(r.x), "=f"(r.y) : "l"(v));
    return r;
}
__device__ __forceinline__ void fma2(unsigned long long& d,
                                     unsigned long long a,
                                     unsigned long long b) {
    asm("fma.rn.f32x2 %0, %1, %2, %0;" : "+l"(d) : "l"(a), "l"(b));
}

// ---------------- degree counting ----------------
__global__ __launch_bounds__(256) void k_count(const int* __restrict__ ei) {
    int e = blockIdx.x * 256 + threadIdx.x;
    if (e >= NE) return;
    atomicAdd(&g_cntf[ei[e]], 1);
    atomicAdd(&g_cntr[ei[NE + e]], 1);
}

__global__ __launch_bounds__(256) void k_deg() {
    int n = blockIdx.x * 256 + threadIdx.x;
    if (n >= NN) return;
    float df = (float)g_cntf[n] + 1.0f;
    float dr = (float)g_cntr[n] + 1.0f;
    g_disf[n] = rsqrtf(df);
    g_disr[n] = rsqrtf(dr);
    g_idegf[n] = 1.0f / df;
    g_idegr[n] = 1.0f / dr;
}

// ---------------- exclusive scan ----------------
__global__ __launch_bounds__(256) void k_scan1(const int* __restrict__ cnt,
                                               int* __restrict__ off,
                                               int* __restrict__ bsum) {
    __shared__ int wsum[8];
    int tid = threadIdx.x, lane = tid & 31, w = tid >> 5;
    int base = blockIdx.x * 1024 + tid * 4;
    int v0 = (base + 0 < NN) ? cnt[base + 0] : 0;
    int v1 = (base + 1 < NN) ? cnt[base + 1] : 0;
    int v2 = (base + 2 < NN) ? cnt[base + 2] : 0;
    int v3 = (base + 3 < NN) ? cnt[base + 3] : 0;
    int s = v0 + v1 + v2 + v3;
    int x = s;
#pragma unroll
    for (int o = 1; o < 32; o <<= 1) {
        int y = __shfl_up_sync(0xffffffffu, x, o);
        if (lane >= o) x += y;
    }
    if (lane == 31) wsum[w] = x;
    __syncthreads();
    if (tid == 0) {
        int r = 0;
#pragma unroll
        for (int j = 0; j < 8; j++) { int t = wsum[j]; wsum[j] = r; r += t; }
        bsum[blockIdx.x] = r;
    }
    __syncthreads();
    int ex = wsum[w] + x - s;
    if (base + 0 < NN) off[base + 0] = ex;
    if (base + 1 < NN) off[base + 1] = ex + v0;
    if (base + 2 < NN) off[base + 2] = ex + v0 + v1;
    if (base + 3 < NN) off[base + 3] = ex + v0 + v1 + v2;
}

__global__ __launch_bounds__(256) void k_scan2(int* __restrict__ bsum, int nb) {
    __shared__ int sm[256];
    int tid = threadIdx.x;
    int v = (tid < nb) ? bsum[tid] : 0;
    sm[tid] = v;
    __syncthreads();
#pragma unroll
    for (int o = 1; o < 256; o <<= 1) {
        int t = (tid >= o) ? sm[tid - o] : 0;
        __syncthreads();
        sm[tid] += t;
        __syncthreads();
    }
    if (tid < nb) bsum[tid] = sm[tid] - v;
}

__global__ __launch_bounds__(256) void k_scan3(int* __restrict__ off,
                                               const int* __restrict__ bsum) {
    int add = bsum[blockIdx.x];
    int base = blockIdx.x * 1024 + threadIdx.x * 4;
#pragma unroll
    for (int i = 0; i < 4; i++)
        if (base + i < NN) off[base + i] += add;
}

// ---------------- CSR placement with per-edge norms ----------------
__global__ __launch_bounds__(256) void k_place(const int* __restrict__ ei) {
    int e = blockIdx.x * 256 + threadIdx.x;
    if (e >= NE) return;
    int a = __ldg(ei + e);
    int b = __ldg(ei + NE + e);
    float nf = __ldg(&g_disf[a]) * __ldg(&g_disf[b]);
    float nr = __ldg(&g_disr[b]) * __ldg(&g_disr[a]);
    int pf = g_offF[b] + atomicAdd(&g_fillF[b], 1);
    g_csrF[pf] = make_int2(a, __float_as_int(nf));
    int pr = g_offR[a] + atomicAdd(&g_fillR[a], 1);
    g_csrR[pr] = make_int2(b, __float_as_int(nr));
}

// ---------------- encoder stage 1 ----------------
template<int KIN, int KOUT, int NPB>
__global__ __launch_bounds__(256) void k_encA(
    const float* __restrict__ x, const float* __restrict__ W,
    const float* __restrict__ bias, float* __restrict__ tmp, int nNodes)
{
    __shared__ float xs[NPB * KIN];
    int tid = threadIdx.x;
    int base = blockIdx.x * NPB;
    const int NSUB = 256 / KOUT;
#pragma unroll
    for (int i = 0; i < (NPB * KIN + 255) / 256; i++) {
        int idx = tid + i * 256;
        if (idx < NPB * KIN) {
            size_t gidx = (size_t)base * KIN + idx;
            size_t mx = (size_t)nNodes * KIN - 1;
            xs[idx] = x[gidx <= mx ? gidx : mx];
        }
    }
    int j = tid & (KOUT - 1);
    int nsub = tid / KOUT;
    float wcol[KIN];
#pragma unroll
    for (int k = 0; k < KIN; k++) wcol[k] = W[k * KOUT + j];
    float bj = bias[j];
    __syncthreads();
#pragma unroll
    for (int t = 0; t < NPB / NSUB; t++) {
        int n = nsub + t * NSUB;
        float a = bj;
#pragma unroll
        for (int k4 = 0; k4 < KIN; k4 += 4) {
            float4 xv = *(const float4*)&xs[n * KIN + k4];
            a += xv.x * wcol[k4] + xv.y * wcol[k4 + 1]
               + xv.z * wcol[k4 + 2] + xv.w * wcol[k4 + 3];
        }
        if (base + n < nNodes)
            tmp[(size_t)(base + n) * KOUT + j] = leaky(a);
    }
}

// ---------------- register-tiled GEMM: dst = act(src @ W + b) ----------------
template<int KTOT, bool LEAKY, bool WRELU>
__global__ __launch_bounds__(128) void k_mm(
    const float* __restrict__ src, int srcStride, int srcOff, int srcBase,
    const float* __restrict__ W, const float* __restrict__ bias,
    float* __restrict__ dst, int dstStride, int dstOff, int dstBase,
    __half2* __restrict__ yout, int nNodes)
{
    __shared__ float hs[64 * 68];
    __shared__ float ws[64 * 64];
    int tid = threadIdx.x;
    int tb = blockIdx.x * 64;
    int tx = tid & 15, ty = tid >> 4;
    int bn = ty * 8;
    unsigned long long acc[4][4];
#pragma unroll
    for (int a = 0; a < 4; a++)
#pragma unroll
        for (int b = 0; b < 4; b++) acc[a][b] = 0ull;

    int c = tid & 63, r = tid >> 6;
    for (int kc = 0; kc < KTOT; kc += 64) {
        if (kc) __syncthreads();
#pragma unroll
        for (int i = 0; i < 32; i++)
            ws[tid + i * 128] = W[kc * 64 + tid + i * 128];
#pragma unroll
        for (int i = 0; i < 32; i++) {
            int nl = i * 2 + r;
            int g = tb + nl; if (g >= nNodes) g = nNodes - 1;
            hs[c * 68 + nl] = src[(size_t)(srcBase + g) * srcStride + srcOff + kc + c];
        }
        __syncthreads();
#pragma unroll 4
        for (int k = 0; k < 64; k++) {
            float4 wf = *(const float4*)&ws[k * 64 + tx * 4];
            unsigned long long dw0 = dup64(wf.x);
            unsigned long long dw1 = dup64(wf.y);
            unsigned long long dw2 = dup64(wf.z);
            unsigned long long dw3 = dup64(wf.w);
            ulonglong2 hA = *(const ulonglong2*)&hs[k * 68 + bn];
            ulonglong2 hB = *(const ulonglong2*)&hs[k * 68 + bn + 4];
            fma2(acc[0][0], hA.x, dw0); fma2(acc[0][1], hA.x, dw1);
            fma2(acc[0][2], hA.x, dw2); fma2(acc[0][3], hA.x, dw3);
            fma2(acc[1][0], hA.y, dw0); fma2(acc[1][1], hA.y, dw1);
            fma2(acc[1][2], hA.y, dw2); fma2(acc[1][3], hA.y, dw3);
            fma2(acc[2][0], hB.x, dw0); fma2(acc[2][1], hB.x, dw1);
            fma2(acc[2][2], hB.x, dw2); fma2(acc[2][3], hB.x, dw3);
            fma2(acc[3][0], hB.y, dw0); fma2(acc[3][1], hB.y, dw1);
            fma2(acc[3][2], hB.y, dw2); fma2(acc[3][3], hB.y, dw3);
        }
    }
    float4 bv = *(const float4*)&bias[tx * 4];
#pragma unroll
    for (int np = 0; np < 4; np++) {
        int n0 = tb + bn + np * 2;
        float2 v0 = up64(acc[np][0]);
        float2 v1 = up64(acc[np][1]);
        float2 v2 = up64(acc[np][2]);
        float2 v3 = up64(acc[np][3]);
        float4 o0 = make_float4(v0.x + bv.x, v1.x + bv.y, v2.x + bv.z, v3.x + bv.w);
        float4 o1 = make_float4(v0.y + bv.x, v1.y + bv.y, v2.y + bv.z, v3.y + bv.w);
        if (LEAKY) {
            o0 = make_float4(leaky(o0.x), leaky(o0.y), leaky(o0.z), leaky(o0.w));
            o1 = make_float4(leaky(o1.x), leaky(o1.y), leaky(o1.z), leaky(o1.w));
        }
        if (n0 < nNodes) {
            *(float4*)&dst[(size_t)(dstBase + n0) * dstStride + dstOff + tx * 4] = o0;
            if (WRELU) {
                __half2 h0 = __float22half2_rn(make_float2(fmaxf(o0.x, 0.f), fmaxf(o0.y, 0.f)));
                __half2 h1 = __float22half2_rn(make_float2(fmaxf(o0.z, 0.f), fmaxf(o0.w, 0.f)));
                uint2 pk = make_uint2(*(unsigned*)&h0, *(unsigned*)&h1);
                *(uint2*)&yout[(size_t)n0 * 32 + tx * 2] = pk;
            }
        }
        if (n0 + 1 < nNodes) {
            *(float4*)&dst[(size_t)(dstBase + n0 + 1) * dstStride + dstOff + tx * 4] = o1;
            if (WRELU) {
                __half2 h0 = __float22half2_rn(make_float2(fmaxf(o1.x, 0.f), fmaxf(o1.y, 0.f)));
                __half2 h1 = __float22half2_rn(make_float2(fmaxf(o1.z, 0.f), fmaxf(o1.w, 0.f)));
                uint2 pk = make_uint2(*(unsigned*)&h0, *(unsigned*)&h1);
                *(uint2*)&yout[(size_t)(n0 + 1) * 32 + tx * 2] = pk;
            }
        }
    }
}

// ---------------- fused aggregation (fwd + rev) + self terms + LayerNorm + leaky ----------------
__global__ __launch_bounds__(256) void k_agg(
    const float* __restrict__ rootf, const float* __restrict__ rootr,
    const float* __restrict__ lg, const float* __restrict__ lb,
    float* __restrict__ out, int off)
{
    int n = blockIdx.x * 8 + (threadIdx.x >> 5);
    int lane = threadIdx.x & 31;
    int d = lane * 2;
    int begF = g_offF[n], degF = g_cntr[n];   // fwd buckets keyed by col
    int begR = g_offR[n], degR = g_cntf[n];   // rev buckets keyed by row
    float2 af = make_float2(0.f, 0.f);
    float2 ar = make_float2(0.f, 0.f);
    {
        const int2* cs = g_csrF + begF;
        const __half2* Y = g_yf;
        int i = 0;
        for (; i + 4 <= degF; i += 4) {
            int2 e0 = __ldg(cs + i), e1 = __ldg(cs + i + 1);
            int2 e2 = __ldg(cs + i + 2), e3 = __ldg(cs + i + 3);
            float2 v0 = __half22float2(__ldg(Y + (size_t)e0.x * 32 + lane));
            float2 v1 = __half22float2(__ldg(Y + (size_t)e1.x * 32 + lane));
            float2 v2 = __half22float2(__ldg(Y + (size_t)e2.x * 32 + lane));
            float2 v3 = __half22float2(__ldg(Y + (size_t)e3.x * 32 + lane));
            float n0 = __int_as_float(e0.y), n1 = __int_as_float(e1.y);
            float n2 = __int_as_float(e2.y), n3 = __int_as_float(e3.y);
            af.x += v0.x * n0 + v1.x * n1 + v2.x * n2 + v3.x * n3;
            af.y += v0.y * n0 + v1.y * n1 + v2.y * n2 + v3.y * n3;
        }
        for (; i < degF; i++) {
            int2 e0 = __ldg(cs + i);
            float2 v0 = __half22float2(__ldg(Y + (size_t)e0.x * 32 + lane));
            float n0 = __int_as_float(e0.y);
            af.x += v0.x * n0;
            af.y += v0.y * n0;
        }
    }
    {
        const int2* cs = g_csrR + begR;
        const __half2* Y = g_yr;
        int i = 0;
        for (; i + 4 <= degR; i += 4) {
            int2 e0 = __ldg(cs + i), e1 = __ldg(cs + i + 1);
            int2 e2 = __ldg(cs + i + 2), e3 = __ldg(cs + i + 3);
            float2 v0 = __half22float2(__ldg(Y + (size_t)e0.x * 32 + lane));
            float2 v1 = __half22float2(__ldg(Y + (size_t)e1.x * 32 + lane));
            float2 v2 = __half22float2(__ldg(Y + (size_t)e2.x * 32 + lane));
            float2 v3 = __half22float2(__ldg(Y + (size_t)e3.x * 32 + lane));
            float n0 = __int_as_float(e0.y), n1 = __int_as_float(e1.y);
            float n2 = __int_as_float(e2.y), n3 = __int_as_float(e3.y);
            ar.x += v0.x * n0 + v1.x * n1 + v2.x * n2 + v3.x * n3;
            ar.y += v0.y * n0 + v1.y * n1 + v2.y * n2 + v3.y * n3;
        }
        for (; i < degR; i++) {
            int2 e0 = __ldg(cs + i);
            float2 v0 = __half22float2(__ldg(Y + (size_t)e0.x * 32 + lane));
            float n0 = __int_as_float(e0.y);
            ar.x += v0.x * n0;
            ar.y += v0.y * n0;
        }
    }
    size_t o64 = (size_t)n * 64 + d;
    float2 fx = *(const float2*)&g_xf[o64];
    float2 rx = *(const float2*)&g_xr[o64];
    float idf = g_idegf[n], idr = g_idegr[n];
    float s0 = af.x + ar.x + fmaxf(fx.x + rootf[d], 0.f) * idf
                           + fmaxf(rx.x + rootr[d], 0.f) * idr;
    float s1 = af.y + ar.y + fmaxf(fx.y + rootf[d + 1], 0.f) * idf
                           + fmaxf(rx.y + rootr[d + 1], 0.f) * idr;
    float sum = s0 + s1;
#pragma unroll
    for (int o = 16; o > 0; o >>= 1) sum += __shfl_xor_sync(0xffffffffu, sum, o);
    float m = sum * (1.0f / 64.0f);
    float d0 = s0 - m, d1 = s1 - m;
    float sq = d0 * d0 + d1 * d1;
#pragma unroll
    for (int o = 16; o > 0; o >>= 1) sq += __shfl_xor_sync(0xffffffffu, sq, o);
    float inv = rsqrtf(sq * (1.0f / 64.0f) + 1e-5f);
    float o0 = leaky(d0 * inv * lg[d] + lb[d]);
    float o1 = leaky(d1 * inv * lg[d + 1] + lb[d + 1]);
    *(float2*)&out[(size_t)n * 256 + off + d] = make_float2(o0, o1);
}

// ---------------- launch ----------------
extern "C" void kernel_launch(void* const* d_in, const int* in_sizes, int n_in,
                              void* d_out, int out_size) {
    const float* x     = (const float*)d_in[0];
    const float* xnet  = (const float*)d_in[1];
    const int*   ei    = (const int*)  d_in[2];
    const float* e1W   = (const float*)d_in[3];
    const float* e1b   = (const float*)d_in[4];
    const float* e2W   = (const float*)d_in[5];
    const float* e2b   = (const float*)d_in[6];
    const float* n1W   = (const float*)d_in[7];
    const float* n1b   = (const float*)d_in[8];
    const float* n2W   = (const float*)d_in[9];
    const float* n2b   = (const float*)d_in[10];
    const float* convW = (const float*)d_in[11];
    const float* convb = (const float*)d_in[12];
    const float* convr = (const float*)d_in[13];
    const float* reW   = (const float*)d_in[14];
    const float* reb   = (const float*)d_in[15];
    const float* rer   = (const float*)d_in[16];
    const float* lng   = (const float*)d_in[17];
    const float* lnb   = (const float*)d_in[18];
    float* out = (float*)d_out;

    void *pcf, *pcr, *pff, *pfr, *poF, *poR, *pbF, *pbR, *pxf, *pxr, *pyf, *pyr, *ptmp, *ptmpn;
    cudaGetSymbolAddress(&pcf, g_cntf);
    cudaGetSymbolAddress(&pcr, g_cntr);
    cudaGetSymbolAddress(&pff, g_fillF);
    cudaGetSymbolAddress(&pfr, g_fillR);
    cudaGetSymbolAddress(&poF, g_offF);
    cudaGetSymbolAddress(&poR, g_offR);
    cudaGetSymbolAddress(&pbF, g_bsF);
    cudaGetSymbolAddress(&pbR, g_bsR);
    cudaGetSymbolAddress(&pxf, g_xf);
    cudaGetSymbolAddress(&pxr, g_xr);
    cudaGetSymbolAddress(&pyf, g_yf);
    cudaGetSymbolAddress(&pyr, g_yr);
    cudaGetSymbolAddress(&ptmp, g_tmp);
    cudaGetSymbolAddress(&ptmpn, g_tmpn);

    static cudaStream_t s2 = []() {
        cudaStream_t s; cudaStreamCreateWithFlags(&s, cudaStreamNonBlocking); return s;
    }();
    auto mkev = []() { cudaEvent_t e; cudaEventCreateWithFlags(&e, cudaEventDisableTiming); return e; };
    static cudaEvent_t evF = mkev();
    static cudaEvent_t evEnc = mkev();
    static cudaEvent_t evL[3] = {mkev(), mkev(), mkev()};
    static cudaEvent_t evR[3] = {mkev(), mkev(), mkev()};

    cudaEventRecord(evF, 0);
    cudaStreamWaitEvent(s2, evF, 0);

    // ---- branch B (side stream): CSR build ----
    cudaMemsetAsync(pcf, 0, NN * sizeof(int), s2);
    cudaMemsetAsync(pcr, 0, NN * sizeof(int), s2);
    cudaMemsetAsync(pff, 0, NN * sizeof(int), s2);
    cudaMemsetAsync(pfr, 0, NN * sizeof(int), s2);
    k_count<<<(NE + 255) / 256, 256, 0, s2>>>(ei);
    k_deg<<<(NN + 255) / 256, 256, 0, s2>>>();
    k_scan1<<<NSCANB, 256, 0, s2>>>((const int*)pcr, (int*)poF, (int*)pbF);
    k_scan1<<<NSCANB, 256, 0, s2>>>((const int*)pcf, (int*)poR, (int*)pbR);
    k_scan2<<<1, 256, 0, s2>>>((int*)pbF, NSCANB);
    k_scan2<<<1, 256, 0, s2>>>((int*)pbR, NSCANB);
    k_scan3<<<NSCANB, 256, 0, s2>>>((int*)poF, (const int*)pbF);
    k_scan3<<<NSCANB, 256, 0, s2>>>((int*)poR, (const int*)pbR);
    k_place<<<(NE + 255) / 256, 256, 0, s2>>>(ei);

    // ---- branch A (main stream): encoders ----
    k_encA<16, 128, 32><<<N_INST / 32, 256>>>(x, e1W, e1b, (float*)ptmp, N_INST);
    k_mm<128, true, false><<<(N_INST + 63) / 64, 128>>>(
        (const float*)ptmp, 128, 0, 0, e2W, e2b, out, 256, 0, 0, nullptr, N_INST);
    k_encA<8, 64, 32><<<(N_NETN + 31) / 32, 256>>>(xnet, n1W, n1b, (float*)ptmpn, N_NETN);
    k_mm<64, true, false><<<(N_NETN + 63) / 64, 128>>>(
        (const float*)ptmpn, 64, 0, 0, n2W, n2b, out, 256, 0, N_INST, nullptr, N_NETN);
    cudaEventRecord(evEnc, 0);

    // ---- layers: (mm_f on main || mm_r on s2) -> fused agg on main ----
    for (int l = 0; l < 3; l++) {
        cudaEvent_t ready = (l == 0) ? evEnc : evL[l - 1];
        cudaStreamWaitEvent(s2, ready, 0);   // s2 already ordered after CSR place
        k_mm<64, false, true><<<(NN + 63) / 64, 128, 0, s2>>>(
            out, 256, l * 64, 0, reW + l * 4096, reb + l * 64,
            (float*)pxr, 64, 0, 0, (__half2*)pyr, NN);
        cudaEventRecord(evR[l], s2);

        k_mm<64, false, true><<<(NN + 63) / 64, 128>>>(
            out, 256, l * 64, 0, convW + l * 4096, convb + l * 64,
            (float*)pxf, 64, 0, 0, (__half2*)pyf, NN);
        cudaStreamWaitEvent(0, evR[l], 0);
        k_agg<<<NN / 8, 256>>>(convr + l * 64, rer + l * 64,
                               lng + l * 64, lnb + l * 64,
                               out, (l + 1) * 64);
        cudaEventRecord(evL[l], 0);
    }
}